// round 13
// baseline (speedup 1.0000x reference)
#include <cuda_runtime.h>
#include <cuda_fp16.h>
#include <cstdint>
#include <math.h>

#define BATCH 16
#define SEQ   512
#define DIM   2048
#define NH    16
#define NG    4
#define HD    128
#define MROWS (BATCH*SEQ)   // 8192
#define KVD   (NG*HD)       // 512
#define NQKV  (DIM + 2*KVD) // 3072

// ---------------------------------------------------------------------------
// scratch (device globals — no allocation allowed)
// ---------------------------------------------------------------------------
__device__ __half g_xhi[(size_t)MROWS * DIM];
__device__ __half g_aoh[(size_t)MROWS * DIM];   // attn out fp16 (b,s,H,hd)
__device__ __half g_wh[(size_t)NQKV * DIM];     // [Wq^T; Wk^T; Wv^T] fp16
__device__ __half g_woh[(size_t)DIM * DIM];     // Wo^T fp16
__device__ float  g_bqkv[NQKV];                 // [bq; bk; bv]

// attention operand buffers, (b, head, s, hd) layout, plain fp16
__device__ __half g_qah[(size_t)MROWS * DIM];
__device__ __half g_kah[(size_t)MROWS * KVD];
__device__ __half g_vah[(size_t)MROWS * KVD];

// ---------------------------------------------------------------------------
// helpers
// ---------------------------------------------------------------------------
__device__ __forceinline__ uint32_t smem_to_u32(const void* p) {
    uint32_t a;
    asm("{ .reg .u64 t; cvta.to.shared.u64 t, %1; cvt.u32.u64 %0, t; }" : "=r"(a) : "l"(p));
    return a;
}
#define SMEM_SWIZZLE_128B(bo) ((bo) ^ (((bo) >> 3) & 0x70))

__device__ __forceinline__ void cp16(uint32_t s, const void* g) {
    asm volatile("cp.async.cg.shared.global [%0], [%1], 16;" :: "r"(s), "l"(g) : "memory");
}
#define CP_COMMIT() asm volatile("cp.async.commit_group;" ::: "memory")
#define CP_WAIT2()  asm volatile("cp.async.wait_group 2;" ::: "memory")
__device__ __forceinline__ void ldm4(uint32_t* r, uint32_t a) {
    asm volatile("ldmatrix.sync.aligned.m8n8.x4.shared.b16 {%0,%1,%2,%3}, [%4];"
                 : "=r"(r[0]), "=r"(r[1]), "=r"(r[2]), "=r"(r[3]) : "r"(a));
}
__device__ __forceinline__ void ldm4t(uint32_t* r, uint32_t a) {
    asm volatile("ldmatrix.sync.aligned.m8n8.x4.trans.shared.b16 {%0,%1,%2,%3}, [%4];"
                 : "=r"(r[0]), "=r"(r[1]), "=r"(r[2]), "=r"(r[3]) : "r"(a));
}
__device__ __forceinline__ void mma16816(float* d, const uint32_t* a, const uint32_t* b) {
    asm volatile(
        "mma.sync.aligned.m16n8k16.row.col.f32.f16.f16.f32 "
        "{%0,%1,%2,%3},{%4,%5,%6,%7},{%8,%9},{%0,%1,%2,%3};"
        : "+f"(d[0]), "+f"(d[1]), "+f"(d[2]), "+f"(d[3])
        : "r"(a[0]), "r"(a[1]), "r"(a[2]), "r"(a[3]), "r"(b[0]), "r"(b[1]));
}
__device__ __forceinline__ uint32_t pk2h(float a, float b) {
    __half2 h = __floats2half2_rn(a, b);
    return *reinterpret_cast<uint32_t*>(&h);
}

// ---------------------------------------------------------------------------
// convert fp32 -> fp16
// ---------------------------------------------------------------------------
__global__ __launch_bounds__(256) void convert_h(
    const float* __restrict__ in, __half* __restrict__ hi, int n4)
{
    int i = blockIdx.x * 256 + threadIdx.x;
    if (i >= n4) return;
    float4 v = ((const float4*)in)[i];
    uint2 ph;
    ph.x = pk2h(v.x, v.y); ph.y = pk2h(v.z, v.w);
    ((uint2*)hi)[i] = ph;
}

// ---------------------------------------------------------------------------
// W [K, N] fp32 -> W^T [N, K] fp16
// ---------------------------------------------------------------------------
__global__ __launch_bounds__(256) void transpose_h(
    const float* __restrict__ W, __half* __restrict__ Th, int K, int N)
{
    __shared__ float tile[32][33];
    int n0 = blockIdx.x * 32, k0 = blockIdx.y * 32;
    int tx = threadIdx.x, ty = threadIdx.y;   // 32 x 8
    #pragma unroll
    for (int j = ty; j < 32; j += 8)
        tile[j][tx] = W[(size_t)(k0 + j) * N + n0 + tx];
    __syncthreads();
    #pragma unroll
    for (int j = ty; j < 32; j += 8)
        Th[(size_t)(n0 + j) * K + k0 + tx] = __float2half_rn(tile[tx][j]);
}

__global__ __launch_bounds__(256) void bias_concat(
    const float* __restrict__ bq, const float* __restrict__ bk,
    const float* __restrict__ bv, float* __restrict__ o)
{
    int i = blockIdx.x * 256 + threadIdx.x;
    if (i < DIM) o[i] = bq[i];
    else if (i < DIM + KVD) o[i] = bk[i - DIM];
    else if (i < NQKV) o[i] = bv[i - DIM - KVD];
}

// ---------------------------------------------------------------------------
// tile config — plain fp16 GEMM, stage = AH 16K + BH 16K, 3-stage
// ---------------------------------------------------------------------------
#define BM 128
#define BN 128
#define BK 64
#define NCH (DIM / BK)   // 32
#define QSTG_BYTES 32768
#define Q_OFF_AH 0
#define Q_OFF_BH 16384
#define QGEMM_SMEM (3 * QSTG_BYTES)   // 98304
#define NPERSIST  296                 // 148 SMs x 2 CTAs

#define QK_NTILES ((NQKV / BN) * (MROWS / BM))   // 24 x 64 = 1536
#define WO_NTILES ((DIM / BN) * (MROWS / BM))    // 16 x 64 = 1024

// ---------------------------------------------------------------------------
// Persistent fused QKV GEMM + RMSNorm + RoPE. Plain fp16; 2 CTAs/SM.
// ---------------------------------------------------------------------------
__global__ __launch_bounds__(256, 2) void gemm_qkv(
    const __half* __restrict__ Ahg, const __half* __restrict__ Bhg,
    const float* __restrict__ bias,
    const float* __restrict__ qns, const float* __restrict__ kns,
    __half* __restrict__ qah, __half* __restrict__ kah,
    __half* __restrict__ vah)
{
    extern __shared__ char sm[];
    uint32_t sb = smem_to_u32(sm);
    int tid = threadIdx.x, lane = tid & 31, wid = tid >> 5;
    int wm = wid & 1, wn = wid >> 1;

    for (int tile = blockIdx.x; tile < QK_NTILES; tile += gridDim.x) {
        int hb = tile % (NQKV / BN);          // 0..23
        int by = (tile / (NQKV / BN)) * BM;
        int bx = hb * BN;

        auto load_stage = [&](int s, int kt) {
            int k0 = kt * BK;
            uint32_t base = sb + s * QSTG_BYTES;
            #pragma unroll
            for (int t = 0; t < 4; t++) {
                int idx = tid + t * 256;
                int r = idx >> 3, c16 = idx & 7;
                uint32_t swz = SMEM_SWIZZLE_128B((uint32_t)(r * 128 + c16 * 16));
                cp16(base + Q_OFF_AH + swz, Ahg + (size_t)(by + r) * DIM + k0 + c16 * 8);
                cp16(base + Q_OFF_BH + swz, Bhg + (size_t)(bx + r) * DIM + k0 + c16 * 8);
            }
        };

        float d[4][4][4];
        #pragma unroll
        for (int i = 0; i < 4; i++)
            #pragma unroll
            for (int j = 0; j < 4; j++)
                #pragma unroll
                for (int q = 0; q < 4; q++) d[i][j][q] = 0.f;

        load_stage(0, 0); CP_COMMIT();
        load_stage(1, 1); CP_COMMIT();
        load_stage(2, 2); CP_COMMIT();

        for (int kt = 0; kt < NCH; kt++) {
            CP_WAIT2();
            __syncthreads();

            int s = kt % 3;
            uint32_t base = sb + s * QSTG_BYTES;
            int arow = wm * 64 + (lane & 15);
            int bro  = wn * 32 + (lane & 7) + ((lane >> 4) << 3);
            int bkh  = ((lane >> 3) & 1) << 3;

            #pragma unroll
            for (int ks = 0; ks < 4; ks++) {
                int acol = ks * 16 + ((lane >> 4) << 3);
                uint32_t ah[4][4], bh[4][2];
                #pragma unroll
                for (int mf = 0; mf < 4; mf++) {
                    uint32_t off = SMEM_SWIZZLE_128B(
                        (uint32_t)((arow + mf * 16) * 128 + acol * 2));
                    ldm4(ah[mf], base + Q_OFF_AH + off);
                }
                #pragma unroll
                for (int j2 = 0; j2 < 2; j2++) {
                    uint32_t off = SMEM_SWIZZLE_128B(
                        (uint32_t)((bro + j2 * 16) * 128 + (ks * 16 + bkh) * 2));
                    uint32_t r[4];
                    ldm4(r, base + Q_OFF_BH + off);
                    bh[j2 * 2][0] = r[0]; bh[j2 * 2][1] = r[1];
                    bh[j2 * 2 + 1][0] = r[2]; bh[j2 * 2 + 1][1] = r[3];
                }
                #pragma unroll
                for (int mf = 0; mf < 4; mf++)
                    #pragma unroll
                    for (int nf = 0; nf < 4; nf++)
                        mma16816(d[mf][nf], ah[mf], bh[nf]);
            }
            __syncthreads();

            if (kt + 3 < NCH) load_stage(s, kt + 3);
            CP_COMMIT();
        }

        // ---------------- fused epilogue ----------------
        bool needs_norm = (hb < 20);

        int c0 = wn * 32 + (lane & 3) * 2;
        #pragma unroll
        for (int mf = 0; mf < 4; mf++)
            #pragma unroll
            for (int nf = 0; nf < 4; nf++) {
                int c = c0 + nf * 8;
                float b0 = bias[bx + c], b1 = bias[bx + c + 1];
                d[mf][nf][0] += b0; d[mf][nf][1] += b1;
                d[mf][nf][2] += b0; d[mf][nf][3] += b1;
            }

        float* ss = (float*)sm;          // [128][4] partial row sums
        __syncthreads();                 // stage reads done before ss overwrite

        if (needs_norm) {
            #pragma unroll
            for (int mf = 0; mf < 4; mf++) {
                float pA = 0.f, pB = 0.f;
                #pragma unroll
                for (int nf = 0; nf < 4; nf++) {
                    pA += d[mf][nf][0] * d[mf][nf][0] + d[mf][nf][1] * d[mf][nf][1];
                    pB += d[mf][nf][2] * d[mf][nf][2] + d[mf][nf][3] * d[mf][nf][3];
                }
                pA += __shfl_xor_sync(0xffffffffu, pA, 1);
                pA += __shfl_xor_sync(0xffffffffu, pA, 2);
                pB += __shfl_xor_sync(0xffffffffu, pB, 1);
                pB += __shfl_xor_sync(0xffffffffu, pB, 2);
                if ((lane & 3) == 0) {
                    int lr = wm * 64 + mf * 16 + (lane >> 2);
                    ss[lr * 4 + wn] = pA;
                    ss[(lr + 8) * 4 + wn] = pB;
                }
            }
        }
        __syncthreads();

        const float* nsc = (hb < 16) ? qns : kns;
        float esc = (hb < 16) ? (1.0f / (float)HD) : 1.0f;
        __half* oph;
        int headmul;
        if (hb < 16)      { oph = qah; headmul = NH; }
        else if (hb < 20) { oph = kah; headmul = NG; }
        else              { oph = vah; headmul = NG; }
        int head = (hb < 16) ? hb : ((hb < 20) ? hb - 16 : hb - 20);

        #pragma unroll
        for (int mf = 0; mf < 4; mf++) {
            int lr = wm * 64 + mf * 16 + (lane >> 2);
            int rowA = by + lr, rowB = rowA + 8;
            int posA = rowA & (SEQ - 1), posB = rowB & (SEQ - 1);
            int bA = rowA >> 9, bB = rowB >> 9;
            float rinvA = 1.f, rinvB = 1.f;
            if (needs_norm) {
                float sA = ss[lr * 4] + ss[lr * 4 + 1] + ss[lr * 4 + 2] + ss[lr * 4 + 3];
                float sB = ss[(lr + 8) * 4] + ss[(lr + 8) * 4 + 1] +
                           ss[(lr + 8) * 4 + 2] + ss[(lr + 8) * 4 + 3];
                rinvA = rsqrtf(sA * (1.0f / HD) + 1e-6f);
                rinvB = rsqrtf(sB * (1.0f / HD) + 1e-6f);
            }
            size_t obA = ((size_t)(bA * headmul + head) * SEQ + posA) * HD;
            size_t obB = ((size_t)(bB * headmul + head) * SEQ + posB) * HD;
            #pragma unroll
            for (int nf = 0; nf < 4; nf++) {
                int c = c0 + nf * 8;
                if (needs_norm) {
                    float sc0 = nsc[c], sc1 = nsc[c + 1];
                    float invf = __expf(-(float)(c >> 1) * (9.210340371976184f / 64.0f));
                    float snA, csA, snB, csB;
                    __sincosf((float)posA * invf, &snA, &csA);
                    __sincosf((float)posB * invf, &snB, &csB);
                    float xA1 = d[mf][nf][0] * rinvA * sc0;
                    float xA2 = d[mf][nf][1] * rinvA * sc1;
                    float xB1 = d[mf][nf][2] * rinvB * sc0;
                    float xB2 = d[mf][nf][3] * rinvB * sc1;
                    *(__half2*)&oph[obA + c] = __floats2half2_rn(
                        (xA1 * csA - xA2 * snA) * esc, (xA1 * snA + xA2 * csA) * esc);
                    *(__half2*)&oph[obB + c] = __floats2half2_rn(
                        (xB1 * csB - xB2 * snB) * esc, (xB1 * snB + xB2 * csB) * esc);
                } else {
                    *(__half2*)&vah[obA + c] = __floats2half2_rn(d[mf][nf][0], d[mf][nf][1]);
                    *(__half2*)&vah[obB + c] = __floats2half2_rn(d[mf][nf][2], d[mf][nf][3]);
                }
            }
        }
        __syncthreads();   // ss reads done before next tile's stage fill
    }
}

// ---------------------------------------------------------------------------
// Persistent Wo GEMM: plain fp16, bias, fp32 output; 2 CTAs/SM.
// ---------------------------------------------------------------------------
__global__ __launch_bounds__(256, 2) void gemm_wo(
    const __half* __restrict__ Ahg, const __half* __restrict__ Bhg,
    const float* __restrict__ bias, float* __restrict__ C, int N)
{
    extern __shared__ char sm[];
    uint32_t sb = smem_to_u32(sm);
    int tid = threadIdx.x, lane = tid & 31, wid = tid >> 5;
    int wm = wid & 1, wn = wid >> 1;

    for (int tile = blockIdx.x; tile < WO_NTILES; tile += gridDim.x) {
        int bx = (tile % (DIM / BN)) * BN;
        int by = (tile / (DIM / BN)) * BM;

        auto load_stage = [&](int s, int kt) {
            int k0 = kt * BK;
            uint32_t base = sb + s * QSTG_BYTES;
            #pragma unroll
            for (int t = 0; t < 4; t++) {
                int idx = tid + t * 256;
                int r = idx >> 3, c16 = idx & 7;
                uint32_t swz = SMEM_SWIZZLE_128B((uint32_t)(r * 128 + c16 * 16));
                cp16(base + Q_OFF_AH + swz, Ahg + (size_t)(by + r) * DIM + k0 + c16 * 8);
                cp16(base + Q_OFF_BH + swz, Bhg + (size_t)(bx + r) * DIM + k0 + c16 * 8);
            }
        };

        float d[4][4][4];
        #pragma unroll
        for (int i = 0; i < 4; i++)
            #pragma unroll
            for (int j = 0; j < 4; j++)
                #pragma unroll
                for (int q = 0; q < 4; q++) d[i][j][q] = 0.f;

        load_stage(0, 0); CP_COMMIT();
        load_stage(1, 1); CP_COMMIT();
        load_stage(2, 2); CP_COMMIT();

        for (int kt = 0; kt < NCH; kt++) {
            CP_WAIT2();
            __syncthreads();

            int s = kt % 3;
            uint32_t base = sb + s * QSTG_BYTES;
            int arow = wm * 64 + (lane & 15);
            int bro  = wn * 32 + (lane & 7) + ((lane >> 4) << 3);
            int bkh  = ((lane >> 3) & 1) << 3;

            #pragma unroll
            for (int ks = 0; ks < 4; ks++) {
                int acol = ks * 16 + ((lane >> 4) << 3);
                uint32_t ah[4][4], bh[4][2];
                #pragma unroll
                for (int mf = 0; mf < 4; mf++) {
                    uint32_t off = SMEM_SWIZZLE_128B(
                        (uint32_t)((arow + mf * 16) * 128 + acol * 2));
                    ldm4(ah[mf], base + Q_OFF_AH + off);
                }
                #pragma unroll
                for (int j2 = 0; j2 < 2; j2++) {
                    uint32_t off = SMEM_SWIZZLE_128B(
                        (uint32_t)((bro + j2 * 16) * 128 + (ks * 16 + bkh) * 2));
                    uint32_t r[4];
                    ldm4(r, base + Q_OFF_BH + off);
                    bh[j2 * 2][0] = r[0]; bh[j2 * 2][1] = r[1];
                    bh[j2 * 2 + 1][0] = r[2]; bh[j2 * 2 + 1][1] = r[3];
                }
                #pragma unroll
                for (int mf = 0; mf < 4; mf++)
                    #pragma unroll
                    for (int nf = 0; nf < 4; nf++)
                        mma16816(d[mf][nf], ah[mf], bh[nf]);
            }
            __syncthreads();

            if (kt + 3 < NCH) load_stage(s, kt + 3);
            CP_COMMIT();
        }

        int row0 = by + wm * 64 + (lane >> 2);
        int col0 = bx + wn * 32 + (lane & 3) * 2;
        #pragma unroll
        for (int mf = 0; mf < 4; mf++)
            #pragma unroll
            for (int nf = 0; nf < 4; nf++) {
                int r = row0 + mf * 16;
                int c = col0 + nf * 8;
                float b0 = bias[c], b1 = bias[c + 1];
                float2 v0 = make_float2(d[mf][nf][0] + b0, d[mf][nf][1] + b1);
                float2 v1 = make_float2(d[mf][nf][2] + b0, d[mf][nf][3] + b1);
                *(float2*)&C[(size_t)r * N + c] = v0;
                *(float2*)&C[(size_t)(r + 8) * N + c] = v1;
            }
    }
}

// ---------------------------------------------------------------------------
// HMMA flash attention (unchanged from R12). Plain fp16, 3-stage, 1 CTA/SM.
// ---------------------------------------------------------------------------
#define FA_STG 32768
#define FA_SMEM (32768 + 3 * FA_STG)   // 131072

__global__ __launch_bounds__(256, 1) void flash_attn_hmma(
    const __half* __restrict__ qh, const __half* __restrict__ kh,
    const __half* __restrict__ vh, __half* __restrict__ aoh)
{
    extern __shared__ char sm[];
    uint32_t sb = smem_to_u32(sm);
    int qb = (gridDim.x - 1) - blockIdx.x;
    int h = blockIdx.y, b = blockIdx.z;
    int g = h >> 2;
    int tid = threadIdx.x, lane = tid & 31, wid = tid >> 5;

    const size_t qbase  = ((size_t)(b * NH + h) * SEQ + qb * 128) * HD;
    const size_t kvbase = ((size_t)(b * NG + g) * SEQ) * HD;

    const uint32_t QH = sb;

    auto load_q = [&]() {
        #pragma unroll
        for (int t = 0; t < 8; t++) {
            int idx = tid + t * 256;
            int r = idx >> 4, c16 = idx & 15;
            uint32_t off = (uint32_t)((c16 >> 3) * 16384) +
                           SMEM_SWIZZLE_128B((uint32_t)(r * 128 + (c16 & 7) * 16));
            cp16(QH + off, qh + qbase + (size_t)r * HD + c16 * 8);
        }
    };
    auto load_kv = [&](int s, int kt) {
        uint32_t base = sb + 32768 + s * FA_STG;
        size_t kb = kvbase + (size_t)kt * 64 * HD;
        #pragma unroll
        for (int t = 0; t < 4; t++) {
            int idx = tid + t * 256;
            int r = idx >> 4, c16 = idx & 15;
            uint32_t off = (uint32_t)((c16 >> 3) * 8192) +
                           SMEM_SWIZZLE_128B((uint32_t)(r * 128 + (c16 & 7) * 16));
            size_t go = kb + (size_t)r * HD + c16 * 8;
            cp16(base + off,         kh + go);
            cp16(base + 16384 + off, vh + go);
        }
    };

    int nkt = 2 * qb + 2;
    load_q();
    if (0 < nkt) load_kv(0, 0);
    CP_COMMIT();
    if (1 < nkt) load_kv(1, 1);
    CP_COMMIT();
    if (2 < nkt) load_kv(2, 2);
    CP_COMMIT();

    float o[16][4];
    #pragma unroll
    for (int i = 0; i < 16; i++)
        #pragma unroll
        for (int j = 0; j < 4; j++) o[i][j] = 0.f;
    float mA = -1e30f, mB = -1e30f, lA = 0.f, lB = 0.f;

    int row0 = wid * 16;
    int sq = qb * 128 + row0;

    for (int kt = 0; kt < nkt; kt++) {
        CP_WAIT2();
        __syncthreads();

        int st = kt % 3;
        uint32_t KHb = sb + 32768 + st * FA_STG;
        uint32_t VHb = KHb + 16384;

        bool active = (kt * 64 <= sq + 15);
        if (active) {
            float sc[8][4];
            #pragma unroll
            for (int i = 0; i < 8; i++)
                #pragma unroll
                for (int j = 0; j < 4; j++) sc[i][j] = 0.f;

            int aro  = row0 + (lane & 15);
            int kro  = (lane & 7) + ((lane >> 4) << 3);
            int bkh  = ((lane >> 3) & 1) << 3;

            // S = Q K^T
            #pragma unroll
            for (int ks = 0; ks < 8; ks++) {
                int chk  = ks >> 2;
                int acol = (ks & 3) * 16 + ((lane >> 4) << 3);
                uint32_t aoff = (uint32_t)(chk * 16384) +
                                SMEM_SWIZZLE_128B((uint32_t)(aro * 128 + acol * 2));
                uint32_t ah[4];
                ldm4(ah, QH + aoff);

                int bcol = (ks & 3) * 16 + bkh;
                uint32_t bh[8][2];
                #pragma unroll
                for (int j2 = 0; j2 < 4; j2++) {
                    uint32_t boff = (uint32_t)(chk * 8192) +
                        SMEM_SWIZZLE_128B((uint32_t)((j2 * 16 + kro) * 128 + bcol * 2));
                    uint32_t r[4];
                    ldm4(r, KHb + boff);
                    bh[2*j2][0] = r[0]; bh[2*j2][1] = r[1];
                    bh[2*j2+1][0] = r[2]; bh[2*j2+1][1] = r[3];
                }
                #pragma unroll
                for (int nf = 0; nf < 8; nf++)
                    mma16816(sc[nf], ah, bh[nf]);
            }

            if (kt * 64 + 63 > sq) {
                int rA = sq + (lane >> 2), rB = rA + 8;
                #pragma unroll
                for (int nf = 0; nf < 8; nf++) {
                    int cbase = kt * 64 + nf * 8 + 2 * (lane & 3);
                    if (cbase     > rA) sc[nf][0] = -1e30f;
                    if (cbase + 1 > rA) sc[nf][1] = -1e30f;
                    if (cbase     > rB) sc[nf][2] = -1e30f;
                    if (cbase + 1 > rB) sc[nf][3] = -1e30f;
                }
            }

            float mtA = -1e30f, mtB = -1e30f;
            #pragma unroll
            for (int nf = 0; nf < 8; nf++) {
                mtA = fmaxf(mtA, fmaxf(sc[nf][0], sc[nf][1]));
                mtB = fmaxf(mtB, fmaxf(sc[nf][2], sc[nf][3]));
            }
            mtA = fmaxf(mtA, __shfl_xor_sync(0xffffffffu, mtA, 1));
            mtA = fmaxf(mtA, __shfl_xor_sync(0xffffffffu, mtA, 2));
            mtB = fmaxf(mtB, __shfl_xor_sync(0xffffffffu, mtB, 1));
            mtB = fmaxf(mtB, __shfl_xor_sync(0xffffffffu, mtB, 2));
            float nmA = fmaxf(mA, mtA), nmB = fmaxf(mB, mtB);
            float alA = __expf(mA - nmA), alB = __expf(mB - nmB);

            float suA = 0.f, suB = 0.f;
            #pragma unroll
            for (int nf = 0; nf < 8; nf++) {
                sc[nf][0] = __expf(sc[nf][0] - nmA); suA += sc[nf][0];
                sc[nf][1] = __expf(sc[nf][1] - nmA); suA += sc[nf][1];
                sc[nf][2] = __expf(sc[nf][2] - nmB); suB += sc[nf][2];
                sc[nf][3] = __expf(sc[nf][3] - nmB); suB += sc[nf][3];
            }
            suA += __shfl_xor_sync(0xffffffffu, suA, 1);
            suA += __shfl_xor_sync(0xffffffffu, suA, 2);
            suB += __shfl_xor_sync(0xffffffffu, suB, 1);
            suB += __shfl_xor_sync(0xffffffffu, suB, 2);
            lA = lA * alA + suA;
            lB = lB * alB + suB;
            mA = nmA; mB = nmB;
            #pragma unroll
            for (int nf = 0; nf < 16; nf++) {
                o[nf][0] *= alA; o[nf][1] *= alA;
                o[nf][2] *= alB; o[nf][3] *= alB;
            }

            // O += P V
            int vro = (lane & 7) + (((lane >> 3) & 1) << 3);
            int vch = (lane >> 4) << 3;
            #pragma unroll
            for (int kf = 0; kf < 4; kf++) {
                uint32_t aPh[4];
                aPh[0] = pk2h(sc[2*kf][0],   sc[2*kf][1]);
                aPh[1] = pk2h(sc[2*kf][2],   sc[2*kf][3]);
                aPh[2] = pk2h(sc[2*kf+1][0], sc[2*kf+1][1]);
                aPh[3] = pk2h(sc[2*kf+1][2], sc[2*kf+1][3]);
                #pragma unroll
                for (int j2 = 0; j2 < 8; j2++) {
                    int chk  = j2 >> 2;
                    int wcol = (j2 & 3) * 16 + vch;
                    uint32_t voff = (uint32_t)(chk * 8192) +
                        SMEM_SWIZZLE_128B((uint32_t)((kf * 16 + vro) * 128 + wcol * 2));
                    uint32_t rh[4];
                    ldm4t(rh, VHb + voff);
                    uint32_t bh0[2] = {rh[0], rh[1]}, bh1[2] = {rh[2], rh[3]};
                    mma16816(o[2*j2],   aPh, bh0);
                    mma16816(o[2*j2+1], aPh, bh1);
                }
            }
        }
        __syncthreads();

        if (kt + 3 < nkt) load_kv(kt % 3, kt + 3);
        CP_COMMIT();
    }

    float rlA = 1.0f / lA, rlB = 1.0f / lB;
    int sA = sq + (lane >> 2), sB = sA + 8;
    size_t oA = ((size_t)(b * SEQ + sA) * NH + h) * HD;
    size_t oB = ((size_t)(b * SEQ + sB) * NH + h) * HD;
    #pragma unroll
    for (int nf = 0; nf < 16; nf++) {
        int hd = nf * 8 + 2 * (lane & 3);
        *(__half2*)&aoh[oA + hd] = __floats2half2_rn(o[nf][0] * rlA, o[nf][1] * rlA);
        *(__half2*)&aoh[oB + hd] = __floats2half2_rn(o[nf][2] * rlB, o[nf][3] * rlB);
    }
}

// ---------------------------------------------------------------------------
extern "C" void kernel_launch(void* const* d_in, const int* in_sizes, int n_in,
                              void* d_out, int out_size)
{
    const float* x   = (const float*)d_in[0];
    const float* Wq  = (const float*)d_in[1];
    const float* bq  = (const float*)d_in[2];
    const float* Wk  = (const float*)d_in[3];
    const float* bk  = (const float*)d_in[4];
    const float* Wv  = (const float*)d_in[5];
    const float* bv  = (const float*)d_in[6];
    const float* Wo  = (const float*)d_in[7];
    const float* bo  = (const float*)d_in[8];
    const float* qns = (const float*)d_in[9];
    const float* kns = (const float*)d_in[10];
    float* out = (float*)d_out;

    __half *xhi, *aoh, *wh, *woh;
    __half *qah, *kah, *vah;
    float* bqkv;
    cudaGetSymbolAddress((void**)&xhi, g_xhi);
    cudaGetSymbolAddress((void**)&aoh, g_aoh);
    cudaGetSymbolAddress((void**)&wh,  g_wh);
    cudaGetSymbolAddress((void**)&woh, g_woh);
    cudaGetSymbolAddress((void**)&bqkv, g_bqkv);
    cudaGetSymbolAddress((void**)&qah, g_qah);
    cudaGetSymbolAddress((void**)&kah, g_kah);
    cudaGetSymbolAddress((void**)&vah, g_vah);

    cudaFuncSetAttribute(gemm_qkv, cudaFuncAttributeMaxDynamicSharedMemorySize, QGEMM_SMEM);
    cudaFuncSetAttribute(gemm_wo, cudaFuncAttributeMaxDynamicSharedMemorySize, QGEMM_SMEM);
    cudaFuncSetAttribute(flash_attn_hmma, cudaFuncAttributeMaxDynamicSharedMemorySize, FA_SMEM);

    const int n4 = MROWS * DIM / 4;

    // conversions
    convert_h<<<(n4 + 255) / 256, 256>>>(x, xhi, n4);
    transpose_h<<<dim3(DIM / 32, DIM / 32), dim3(32, 8)>>>(Wq, wh, DIM, DIM);
    transpose_h<<<dim3(KVD / 32, DIM / 32), dim3(32, 8)>>>(
        Wk, wh + (size_t)DIM * DIM, DIM, KVD);
    transpose_h<<<dim3(KVD / 32, DIM / 32), dim3(32, 8)>>>(
        Wv, wh + (size_t)(DIM + KVD) * DIM, DIM, KVD);
    transpose_h<<<dim3(DIM / 32, DIM / 32), dim3(32, 8)>>>(Wo, woh, DIM, DIM);
    bias_concat<<<(NQKV + 255) / 256, 256>>>(bq, bk, bv, bqkv);

    // persistent fused QKV projection + rmsnorm + rope (q carries full 1/hd)
    gemm_qkv<<<NPERSIST, 256, QGEMM_SMEM>>>(
        xhi, wh, bqkv, qns, kns, qah, kah, vah);

    // attention (HMMA, plain fp16)
    flash_attn_hmma<<<dim3(SEQ / 128, NH, BATCH), 256, FA_SMEM>>>(
        qah, kah, vah, aoh);

    // persistent output projection (plain fp16)
    gemm_wo<<<NPERSIST, 256, QGEMM_SMEM>>>(
        aoh, woh, bo, out, DIM);
}

// round 14
// speedup vs baseline: 1.0392x; 1.0392x over previous
#include <cuda_runtime.h>
#include <cuda_fp16.h>
#include <cstdint>
#include <math.h>

#define BATCH 16
#define SEQ   512
#define DIM   2048
#define NH    16
#define NG    4
#define HD    128
#define MROWS (BATCH*SEQ)   // 8192
#define KVD   (NG*HD)       // 512
#define NQKV  (DIM + 2*KVD) // 3072

// ---------------------------------------------------------------------------
// scratch (device globals — no allocation allowed)
// ---------------------------------------------------------------------------
__device__ __half g_xhi[(size_t)MROWS * DIM];
__device__ __half g_aoh[(size_t)MROWS * DIM];   // attn out fp16 (b,s,H,hd)
__device__ __half g_wh[(size_t)NQKV * DIM];     // [Wq^T; Wk^T; Wv^T] fp16
__device__ __half g_woh[(size_t)DIM * DIM];     // Wo^T fp16
__device__ float  g_bqkv[NQKV];                 // [bq; bk; bv]

// attention operand buffers, (b, head, s, hd) layout, plain fp16
__device__ __half g_qah[(size_t)MROWS * DIM];
__device__ __half g_kah[(size_t)MROWS * KVD];
__device__ __half g_vah[(size_t)MROWS * KVD];

// ---------------------------------------------------------------------------
// helpers
// ---------------------------------------------------------------------------
__device__ __forceinline__ uint32_t smem_to_u32(const void* p) {
    uint32_t a;
    asm("{ .reg .u64 t; cvta.to.shared.u64 t, %1; cvt.u32.u64 %0, t; }" : "=r"(a) : "l"(p));
    return a;
}
#define SMEM_SWIZZLE_128B(bo) ((bo) ^ (((bo) >> 3) & 0x70))

__device__ __forceinline__ void cp16(uint32_t s, const void* g) {
    asm volatile("cp.async.cg.shared.global [%0], [%1], 16;" :: "r"(s), "l"(g) : "memory");
}
#define CP_COMMIT() asm volatile("cp.async.commit_group;" ::: "memory")
#define CP_WAIT2()  asm volatile("cp.async.wait_group 2;" ::: "memory")
__device__ __forceinline__ void ldm4(uint32_t* r, uint32_t a) {
    asm volatile("ldmatrix.sync.aligned.m8n8.x4.shared.b16 {%0,%1,%2,%3}, [%4];"
                 : "=r"(r[0]), "=r"(r[1]), "=r"(r[2]), "=r"(r[3]) : "r"(a));
}
__device__ __forceinline__ void ldm4t(uint32_t* r, uint32_t a) {
    asm volatile("ldmatrix.sync.aligned.m8n8.x4.trans.shared.b16 {%0,%1,%2,%3}, [%4];"
                 : "=r"(r[0]), "=r"(r[1]), "=r"(r[2]), "=r"(r[3]) : "r"(a));
}
__device__ __forceinline__ void mma16816(float* d, const uint32_t* a, const uint32_t* b) {
    asm volatile(
        "mma.sync.aligned.m16n8k16.row.col.f32.f16.f16.f32 "
        "{%0,%1,%2,%3},{%4,%5,%6,%7},{%8,%9},{%0,%1,%2,%3};"
        : "+f"(d[0]), "+f"(d[1]), "+f"(d[2]), "+f"(d[3])
        : "r"(a[0]), "r"(a[1]), "r"(a[2]), "r"(a[3]), "r"(b[0]), "r"(b[1]));
}
__device__ __forceinline__ uint32_t pk2h(float a, float b) {
    __half2 h = __floats2half2_rn(a, b);
    return *reinterpret_cast<uint32_t*>(&h);
}

// ---------------------------------------------------------------------------
// convert fp32 -> fp16
// ---------------------------------------------------------------------------
__global__ __launch_bounds__(256) void convert_h(
    const float* __restrict__ in, __half* __restrict__ hi, int n4)
{
    int i = blockIdx.x * 256 + threadIdx.x;
    if (i >= n4) return;
    float4 v = ((const float4*)in)[i];
    uint2 ph;
    ph.x = pk2h(v.x, v.y); ph.y = pk2h(v.z, v.w);
    ((uint2*)hi)[i] = ph;
}

// ---------------------------------------------------------------------------
// Fused weight prep: transpose+convert all four weight matrices (fp32 [K,N]
// -> fp16 [N,K]) and concatenate biases, in ONE launch.
// Block map: [0,4096)   Wq  -> g_wh
//            [4096,5120) Wk -> g_wh + DIM*DIM
//            [5120,6144) Wv -> g_wh + (DIM+KVD)*DIM
//            [6144,10240) Wo -> g_woh
//            [10240,10252) bias concat
// ---------------------------------------------------------------------------
__global__ __launch_bounds__(256) void weight_prep(
    const float* __restrict__ Wq, const float* __restrict__ Wk,
    const float* __restrict__ Wv, const float* __restrict__ Wo,
    const float* __restrict__ bq, const float* __restrict__ bk,
    const float* __restrict__ bv,
    __half* __restrict__ wh, __half* __restrict__ woh,
    float* __restrict__ bqkv)
{
    int id = blockIdx.x;
    if (id >= 10240) {   // bias concat blocks
        int i = (id - 10240) * 256 + threadIdx.x;
        if (i < DIM) bqkv[i] = bq[i];
        else if (i < DIM + KVD) bqkv[i] = bk[i - DIM];
        else if (i < NQKV) bqkv[i] = bv[i - DIM - KVD];
        return;
    }

    const float* W;
    __half* T;
    int N, nb, base;
    if (id < 4096)      { W = Wq; T = wh;                              N = DIM; nb = 64; base = 0; }
    else if (id < 5120) { W = Wk; T = wh + (size_t)DIM * DIM;          N = KVD; nb = 16; base = 4096; }
    else if (id < 6144) { W = Wv; T = wh + (size_t)(DIM + KVD) * DIM;  N = KVD; nb = 16; base = 5120; }
    else                { W = Wo; T = woh;                             N = DIM; nb = 64; base = 6144; }
    int lid = id - base;
    int n0 = (lid % nb) * 32;
    int k0 = (lid / nb) * 32;

    __shared__ float tile[32][33];
    int tx = threadIdx.x & 31, ty = threadIdx.x >> 5;   // 32 x 8
    #pragma unroll
    for (int j = ty; j < 32; j += 8)
        tile[j][tx] = W[(size_t)(k0 + j) * N + n0 + tx];
    __syncthreads();
    #pragma unroll
    for (int j = ty; j < 32; j += 8)
        T[(size_t)(n0 + j) * DIM + k0 + tx] = __float2half_rn(tile[tx][j]);
}

// ---------------------------------------------------------------------------
// tile config — plain fp16 GEMM, stage = AH 16K + BH 16K, 3-stage
// ---------------------------------------------------------------------------
#define BM 128
#define BN 128
#define BK 64
#define NCH (DIM / BK)   // 32
#define QSTG_BYTES 32768
#define Q_OFF_AH 0
#define Q_OFF_BH 16384
#define QGEMM_SMEM (3 * QSTG_BYTES)   // 98304

// ---------------------------------------------------------------------------
// Fused QKV GEMM + RMSNorm + RoPE epilogue. Plain fp16; 2 CTAs/SM.
// ---------------------------------------------------------------------------
__global__ __launch_bounds__(256, 2) void gemm_qkv(
    const __half* __restrict__ Ahg, const __half* __restrict__ Bhg,
    const float* __restrict__ bias,
    const float* __restrict__ qns, const float* __restrict__ kns,
    __half* __restrict__ qah, __half* __restrict__ kah,
    __half* __restrict__ vah)
{
    extern __shared__ char sm[];
    uint32_t sb = smem_to_u32(sm);
    int tid = threadIdx.x, lane = tid & 31, wid = tid >> 5;
    int wm = wid & 1, wn = wid >> 1;
    int bx = blockIdx.x * BN, by = blockIdx.y * BM;

    auto load_stage = [&](int s, int kt) {
        int k0 = kt * BK;
        uint32_t base = sb + s * QSTG_BYTES;
        #pragma unroll
        for (int t = 0; t < 4; t++) {
            int idx = tid + t * 256;
            int r = idx >> 3, c16 = idx & 7;
            uint32_t swz = SMEM_SWIZZLE_128B((uint32_t)(r * 128 + c16 * 16));
            cp16(base + Q_OFF_AH + swz, Ahg + (size_t)(by + r) * DIM + k0 + c16 * 8);
            cp16(base + Q_OFF_BH + swz, Bhg + (size_t)(bx + r) * DIM + k0 + c16 * 8);
        }
    };

    float d[4][4][4];
    #pragma unroll
    for (int i = 0; i < 4; i++)
        #pragma unroll
        for (int j = 0; j < 4; j++)
            #pragma unroll
            for (int q = 0; q < 4; q++) d[i][j][q] = 0.f;

    load_stage(0, 0); CP_COMMIT();
    load_stage(1, 1); CP_COMMIT();
    load_stage(2, 2); CP_COMMIT();

    for (int kt = 0; kt < NCH; kt++) {
        CP_WAIT2();
        __syncthreads();

        int s = kt % 3;
        uint32_t base = sb + s * QSTG_BYTES;
        int arow = wm * 64 + (lane & 15);
        int bro  = wn * 32 + (lane & 7) + ((lane >> 4) << 3);
        int bkh  = ((lane >> 3) & 1) << 3;

        #pragma unroll
        for (int ks = 0; ks < 4; ks++) {
            int acol = ks * 16 + ((lane >> 4) << 3);
            uint32_t ah[4][4], bh[4][2];
            #pragma unroll
            for (int mf = 0; mf < 4; mf++) {
                uint32_t off = SMEM_SWIZZLE_128B(
                    (uint32_t)((arow + mf * 16) * 128 + acol * 2));
                ldm4(ah[mf], base + Q_OFF_AH + off);
            }
            #pragma unroll
            for (int j2 = 0; j2 < 2; j2++) {
                uint32_t off = SMEM_SWIZZLE_128B(
                    (uint32_t)((bro + j2 * 16) * 128 + (ks * 16 + bkh) * 2));
                uint32_t r[4];
                ldm4(r, base + Q_OFF_BH + off);
                bh[j2 * 2][0] = r[0]; bh[j2 * 2][1] = r[1];
                bh[j2 * 2 + 1][0] = r[2]; bh[j2 * 2 + 1][1] = r[3];
            }
            #pragma unroll
            for (int mf = 0; mf < 4; mf++)
                #pragma unroll
                for (int nf = 0; nf < 4; nf++)
                    mma16816(d[mf][nf], ah[mf], bh[nf]);
        }
        __syncthreads();

        if (kt + 3 < NCH) load_stage(s, kt + 3);
        CP_COMMIT();
    }

    // ---------------- fused epilogue ----------------
    int hb = blockIdx.x;             // 0..23
    bool needs_norm = (hb < 20);     // q and k blocks

    int c0 = wn * 32 + (lane & 3) * 2;
    #pragma unroll
    for (int mf = 0; mf < 4; mf++)
        #pragma unroll
        for (int nf = 0; nf < 4; nf++) {
            int c = c0 + nf * 8;
            float b0 = bias[bx + c], b1 = bias[bx + c + 1];
            d[mf][nf][0] += b0; d[mf][nf][1] += b1;
            d[mf][nf][2] += b0; d[mf][nf][3] += b1;
        }

    float* ss = (float*)sm;          // [128][4] partial row sums
    __syncthreads();

    if (needs_norm) {
        #pragma unroll
        for (int mf = 0; mf < 4; mf++) {
            float pA = 0.f, pB = 0.f;
            #pragma unroll
            for (int nf = 0; nf < 4; nf++) {
                pA += d[mf][nf][0] * d[mf][nf][0] + d[mf][nf][1] * d[mf][nf][1];
                pB += d[mf][nf][2] * d[mf][nf][2] + d[mf][nf][3] * d[mf][nf][3];
            }
            pA += __shfl_xor_sync(0xffffffffu, pA, 1);
            pA += __shfl_xor_sync(0xffffffffu, pA, 2);
            pB += __shfl_xor_sync(0xffffffffu, pB, 1);
            pB += __shfl_xor_sync(0xffffffffu, pB, 2);
            if ((lane & 3) == 0) {
                int lr = wm * 64 + mf * 16 + (lane >> 2);
                ss[lr * 4 + wn] = pA;
                ss[(lr + 8) * 4 + wn] = pB;
            }
        }
    }
    __syncthreads();

    const float* nsc = (hb < 16) ? qns : kns;
    float esc = (hb < 16) ? (1.0f / (float)HD) : 1.0f;
    __half* oph;
    int headmul;
    if (hb < 16)      { oph = qah; headmul = NH; }
    else if (hb < 20) { oph = kah; headmul = NG; }
    else              { oph = vah; headmul = NG; }
    int head = (hb < 16) ? hb : ((hb < 20) ? hb - 16 : hb - 20);

    #pragma unroll
    for (int mf = 0; mf < 4; mf++) {
        int lr = wm * 64 + mf * 16 + (lane >> 2);
        int rowA = by + lr, rowB = rowA + 8;
        int posA = rowA & (SEQ - 1), posB = rowB & (SEQ - 1);
        int bA = rowA >> 9, bB = rowB >> 9;
        float rinvA = 1.f, rinvB = 1.f;
        if (needs_norm) {
            float sA = ss[lr * 4] + ss[lr * 4 + 1] + ss[lr * 4 + 2] + ss[lr * 4 + 3];
            float sB = ss[(lr + 8) * 4] + ss[(lr + 8) * 4 + 1] +
                       ss[(lr + 8) * 4 + 2] + ss[(lr + 8) * 4 + 3];
            rinvA = rsqrtf(sA * (1.0f / HD) + 1e-6f);
            rinvB = rsqrtf(sB * (1.0f / HD) + 1e-6f);
        }
        size_t obA = ((size_t)(bA * headmul + head) * SEQ + posA) * HD;
        size_t obB = ((size_t)(bB * headmul + head) * SEQ + posB) * HD;
        #pragma unroll
        for (int nf = 0; nf < 4; nf++) {
            int c = c0 + nf * 8;
            if (needs_norm) {
                float sc0 = nsc[c], sc1 = nsc[c + 1];
                float invf = __expf(-(float)(c >> 1) * (9.210340371976184f / 64.0f));
                float snA, csA, snB, csB;
                __sincosf((float)posA * invf, &snA, &csA);
                __sincosf((float)posB * invf, &snB, &csB);
                float xA1 = d[mf][nf][0] * rinvA * sc0;
                float xA2 = d[mf][nf][1] * rinvA * sc1;
                float xB1 = d[mf][nf][2] * rinvB * sc0;
                float xB2 = d[mf][nf][3] * rinvB * sc1;
                *(__half2*)&oph[obA + c] = __floats2half2_rn(
                    (xA1 * csA - xA2 * snA) * esc, (xA1 * snA + xA2 * csA) * esc);
                *(__half2*)&oph[obB + c] = __floats2half2_rn(
                    (xB1 * csB - xB2 * snB) * esc, (xB1 * snB + xB2 * csB) * esc);
            } else {
                *(__half2*)&vah[obA + c] = __floats2half2_rn(d[mf][nf][0], d[mf][nf][1]);
                *(__half2*)&vah[obB + c] = __floats2half2_rn(d[mf][nf][2], d[mf][nf][3]);
            }
        }
    }
}

// ---------------------------------------------------------------------------
// Wo GEMM: plain fp16 single-product, bias, fp32 output; 2 CTAs/SM.
// ---------------------------------------------------------------------------
__global__ __launch_bounds__(256, 2) void gemm_wo(
    const __half* __restrict__ Ahg, const __half* __restrict__ Bhg,
    const float* __restrict__ bias, float* __restrict__ C, int N)
{
    extern __shared__ char sm[];
    uint32_t sb = smem_to_u32(sm);
    int tid = threadIdx.x, lane = tid & 31, wid = tid >> 5;
    int wm = wid & 1, wn = wid >> 1;
    int bx = blockIdx.x * BN, by = blockIdx.y * BM;

    auto load_stage = [&](int s, int kt) {
        int k0 = kt * BK;
        uint32_t base = sb + s * QSTG_BYTES;
        #pragma unroll
        for (int t = 0; t < 4; t++) {
            int idx = tid + t * 256;
            int r = idx >> 3, c16 = idx & 7;
            uint32_t swz = SMEM_SWIZZLE_128B((uint32_t)(r * 128 + c16 * 16));
            cp16(base + Q_OFF_AH + swz, Ahg + (size_t)(by + r) * DIM + k0 + c16 * 8);
            cp16(base + Q_OFF_BH + swz, Bhg + (size_t)(bx + r) * DIM + k0 + c16 * 8);
        }
    };

    float d[4][4][4];
    #pragma unroll
    for (int i = 0; i < 4; i++)
        #pragma unroll
        for (int j = 0; j < 4; j++)
            #pragma unroll
            for (int q = 0; q < 4; q++) d[i][j][q] = 0.f;

    load_stage(0, 0); CP_COMMIT();
    load_stage(1, 1); CP_COMMIT();
    load_stage(2, 2); CP_COMMIT();

    for (int kt = 0; kt < NCH; kt++) {
        CP_WAIT2();
        __syncthreads();

        int s = kt % 3;
        uint32_t base = sb + s * QSTG_BYTES;
        int arow = wm * 64 + (lane & 15);
        int bro  = wn * 32 + (lane & 7) + ((lane >> 4) << 3);
        int bkh  = ((lane >> 3) & 1) << 3;

        #pragma unroll
        for (int ks = 0; ks < 4; ks++) {
            int acol = ks * 16 + ((lane >> 4) << 3);
            uint32_t ah[4][4], bh[4][2];
            #pragma unroll
            for (int mf = 0; mf < 4; mf++) {
                uint32_t off = SMEM_SWIZZLE_128B(
                    (uint32_t)((arow + mf * 16) * 128 + acol * 2));
                ldm4(ah[mf], base + Q_OFF_AH + off);
            }
            #pragma unroll
            for (int j2 = 0; j2 < 2; j2++) {
                uint32_t off = SMEM_SWIZZLE_128B(
                    (uint32_t)((bro + j2 * 16) * 128 + (ks * 16 + bkh) * 2));
                uint32_t r[4];
                ldm4(r, base + Q_OFF_BH + off);
                bh[j2 * 2][0] = r[0]; bh[j2 * 2][1] = r[1];
                bh[j2 * 2 + 1][0] = r[2]; bh[j2 * 2 + 1][1] = r[3];
            }
            #pragma unroll
            for (int mf = 0; mf < 4; mf++)
                #pragma unroll
                for (int nf = 0; nf < 4; nf++)
                    mma16816(d[mf][nf], ah[mf], bh[nf]);
        }
        __syncthreads();

        if (kt + 3 < NCH) load_stage(s, kt + 3);
        CP_COMMIT();
    }

    int row0 = by + wm * 64 + (lane >> 2);
    int col0 = bx + wn * 32 + (lane & 3) * 2;
    #pragma unroll
    for (int mf = 0; mf < 4; mf++)
        #pragma unroll
        for (int nf = 0; nf < 4; nf++) {
            int r = row0 + mf * 16;
            int c = col0 + nf * 8;
            float b0 = bias[c], b1 = bias[c + 1];
            float2 v0 = make_float2(d[mf][nf][0] + b0, d[mf][nf][1] + b1);
            float2 v1 = make_float2(d[mf][nf][2] + b0, d[mf][nf][3] + b1);
            *(float2*)&C[(size_t)r * N + c] = v0;
            *(float2*)&C[(size_t)(r + 8) * N + c] = v1;
        }
}

// ---------------------------------------------------------------------------
// HMMA flash attention. All operands plain fp16, single-product MMAs.
// smem: Q 32KB + 3 x (K 16K + V 16K) = 128KB
// ---------------------------------------------------------------------------
#define FA_STG 32768
#define FA_SMEM (32768 + 3 * FA_STG)   // 131072

__global__ __launch_bounds__(256, 1) void flash_attn_hmma(
    const __half* __restrict__ qh, const __half* __restrict__ kh,
    const __half* __restrict__ vh, __half* __restrict__ aoh)
{
    extern __shared__ char sm[];
    uint32_t sb = smem_to_u32(sm);
    int qb = (gridDim.x - 1) - blockIdx.x;
    int h = blockIdx.y, b = blockIdx.z;
    int g = h >> 2;
    int tid = threadIdx.x, lane = tid & 31, wid = tid >> 5;

    const size_t qbase  = ((size_t)(b * NH + h) * SEQ + qb * 128) * HD;
    const size_t kvbase = ((size_t)(b * NG + g) * SEQ) * HD;

    const uint32_t QH = sb;

    auto load_q = [&]() {
        #pragma unroll
        for (int t = 0; t < 8; t++) {
            int idx = tid + t * 256;
            int r = idx >> 4, c16 = idx & 15;
            uint32_t off = (uint32_t)((c16 >> 3) * 16384) +
                           SMEM_SWIZZLE_128B((uint32_t)(r * 128 + (c16 & 7) * 16));
            cp16(QH + off, qh + qbase + (size_t)r * HD + c16 * 8);
        }
    };
    auto load_kv = [&](int s, int kt) {
        uint32_t base = sb + 32768 + s * FA_STG;
        size_t kb = kvbase + (size_t)kt * 64 * HD;
        #pragma unroll
        for (int t = 0; t < 4; t++) {
            int idx = tid + t * 256;
            int r = idx >> 4, c16 = idx & 15;
            uint32_t off = (uint32_t)((c16 >> 3) * 8192) +
                           SMEM_SWIZZLE_128B((uint32_t)(r * 128 + (c16 & 7) * 16));
            size_t go = kb + (size_t)r * HD + c16 * 8;
            cp16(base + off,         kh + go);
            cp16(base + 16384 + off, vh + go);
        }
    };

    int nkt = 2 * qb + 2;
    load_q();
    if (0 < nkt) load_kv(0, 0);
    CP_COMMIT();
    if (1 < nkt) load_kv(1, 1);
    CP_COMMIT();
    if (2 < nkt) load_kv(2, 2);
    CP_COMMIT();

    float o[16][4];
    #pragma unroll
    for (int i = 0; i < 16; i++)
        #pragma unroll
        for (int j = 0; j < 4; j++) o[i][j] = 0.f;
    float mA = -1e30f, mB = -1e30f, lA = 0.f, lB = 0.f;

    int row0 = wid * 16;
    int sq = qb * 128 + row0;

    for (int kt = 0; kt < nkt; kt++) {
        CP_WAIT2();
        __syncthreads();

        int st = kt % 3;
        uint32_t KHb = sb + 32768 + st * FA_STG;
        uint32_t VHb = KHb + 16384;

        bool active = (kt * 64 <= sq + 15);
        if (active) {
            float sc[8][4];
            #pragma unroll
            for (int i = 0; i < 8; i++)
                #pragma unroll
                for (int j = 0; j < 4; j++) sc[i][j] = 0.f;

            int aro  = row0 + (lane & 15);
            int kro  = (lane & 7) + ((lane >> 4) << 3);
            int bkh  = ((lane >> 3) & 1) << 3;

            // S = Q K^T
            #pragma unroll
            for (int ks = 0; ks < 8; ks++) {
                int chk  = ks >> 2;
                int acol = (ks & 3) * 16 + ((lane >> 4) << 3);
                uint32_t aoff = (uint32_t)(chk * 16384) +
                                SMEM_SWIZZLE_128B((uint32_t)(aro * 128 + acol * 2));
                uint32_t ah[4];
                ldm4(ah, QH + aoff);

                int bcol = (ks & 3) * 16 + bkh;
                uint32_t bh[8][2];
                #pragma unroll
                for (int j2 = 0; j2 < 4; j2++) {
                    uint32_t boff = (uint32_t)(chk * 8192) +
                        SMEM_SWIZZLE_128B((uint32_t)((j2 * 16 + kro) * 128 + bcol * 2));
                    uint32_t r[4];
                    ldm4(r, KHb + boff);
                    bh[2*j2][0] = r[0]; bh[2*j2][1] = r[1];
                    bh[2*j2+1][0] = r[2]; bh[2*j2+1][1] = r[3];
                }
                #pragma unroll
                for (int nf = 0; nf < 8; nf++)
                    mma16816(sc[nf], ah, bh[nf]);
            }

            if (kt * 64 + 63 > sq) {
                int rA = sq + (lane >> 2), rB = rA + 8;
                #pragma unroll
                for (int nf = 0; nf < 8; nf++) {
                    int cbase = kt * 64 + nf * 8 + 2 * (lane & 3);
                    if (cbase     > rA) sc[nf][0] = -1e30f;
                    if (cbase + 1 > rA) sc[nf][1] = -1e30f;
                    if (cbase     > rB) sc[nf][2] = -1e30f;
                    if (cbase + 1 > rB) sc[nf][3] = -1e30f;
                }
            }

            float mtA = -1e30f, mtB = -1e30f;
            #pragma unroll
            for (int nf = 0; nf < 8; nf++) {
                mtA = fmaxf(mtA, fmaxf(sc[nf][0], sc[nf][1]));
                mtB = fmaxf(mtB, fmaxf(sc[nf][2], sc[nf][3]));
            }
            mtA = fmaxf(mtA, __shfl_xor_sync(0xffffffffu, mtA, 1));
            mtA = fmaxf(mtA, __shfl_xor_sync(0xffffffffu, mtA, 2));
            mtB = fmaxf(mtB, __shfl_xor_sync(0xffffffffu, mtB, 1));
            mtB = fmaxf(mtB, __shfl_xor_sync(0xffffffffu, mtB, 2));
            float nmA = fmaxf(mA, mtA), nmB = fmaxf(mB, mtB);
            float alA = __expf(mA - nmA), alB = __expf(mB - nmB);

            float suA = 0.f, suB = 0.f;
            #pragma unroll
            for (int nf = 0; nf < 8; nf++) {
                sc[nf][0] = __expf(sc[nf][0] - nmA); suA += sc[nf][0];
                sc[nf][1] = __expf(sc[nf][1] - nmA); suA += sc[nf][1];
                sc[nf][2] = __expf(sc[nf][2] - nmB); suB += sc[nf][2];
                sc[nf][3] = __expf(sc[nf][3] - nmB); suB += sc[nf][3];
            }
            suA += __shfl_xor_sync(0xffffffffu, suA, 1);
            suA += __shfl_xor_sync(0xffffffffu, suA, 2);
            suB += __shfl_xor_sync(0xffffffffu, suB, 1);
            suB += __shfl_xor_sync(0xffffffffu, suB, 2);
            lA = lA * alA + suA;
            lB = lB * alB + suB;
            mA = nmA; mB = nmB;
            #pragma unroll
            for (int nf = 0; nf < 16; nf++) {
                o[nf][0] *= alA; o[nf][1] *= alA;
                o[nf][2] *= alB; o[nf][3] *= alB;
            }

            // O += P V
            int vro = (lane & 7) + (((lane >> 3) & 1) << 3);
            int vch = (lane >> 4) << 3;
            #pragma unroll
            for (int kf = 0; kf < 4; kf++) {
                uint32_t aPh[4];
                aPh[0] = pk2h(sc[2*kf][0],   sc[2*kf][1]);
                aPh[1] = pk2h(sc[2*kf][2],   sc[2*kf][3]);
                aPh[2] = pk2h(sc[2*kf+1][0], sc[2*kf+1][1]);
                aPh[3] = pk2h(sc[2*kf+1][2], sc[2*kf+1][3]);
                #pragma unroll
                for (int j2 = 0; j2 < 8; j2++) {
                    int chk  = j2 >> 2;
                    int wcol = (j2 & 3) * 16 + vch;
                    uint32_t voff = (uint32_t)(chk * 8192) +
                        SMEM_SWIZZLE_128B((uint32_t)((kf * 16 + vro) * 128 + wcol * 2));
                    uint32_t rh[4];
                    ldm4t(rh, VHb + voff);
                    uint32_t bh0[2] = {rh[0], rh[1]}, bh1[2] = {rh[2], rh[3]};
                    mma16816(o[2*j2],   aPh, bh0);
                    mma16816(o[2*j2+1], aPh, bh1);
                }
            }
        }
        __syncthreads();

        if (kt + 3 < nkt) load_kv(kt % 3, kt + 3);
        CP_COMMIT();
    }

    float rlA = 1.0f / lA, rlB = 1.0f / lB;
    int sA = sq + (lane >> 2), sB = sA + 8;
    size_t oA = ((size_t)(b * SEQ + sA) * NH + h) * HD;
    size_t oB = ((size_t)(b * SEQ + sB) * NH + h) * HD;
    #pragma unroll
    for (int nf = 0; nf < 16; nf++) {
        int hd = nf * 8 + 2 * (lane & 3);
        *(__half2*)&aoh[oA + hd] = __floats2half2_rn(o[nf][0] * rlA, o[nf][1] * rlA);
        *(__half2*)&aoh[oB + hd] = __floats2half2_rn(o[nf][2] * rlB, o[nf][3] * rlB);
    }
}

// ---------------------------------------------------------------------------
extern "C" void kernel_launch(void* const* d_in, const int* in_sizes, int n_in,
                              void* d_out, int out_size)
{
    const float* x   = (const float*)d_in[0];
    const float* Wq  = (const float*)d_in[1];
    const float* bq  = (const float*)d_in[2];
    const float* Wk  = (const float*)d_in[3];
    const float* bk  = (const float*)d_in[4];
    const float* Wv  = (const float*)d_in[5];
    const float* bv  = (const float*)d_in[6];
    const float* Wo  = (const float*)d_in[7];
    const float* bo  = (const float*)d_in[8];
    const float* qns = (const float*)d_in[9];
    const float* kns = (const float*)d_in[10];
    float* out = (float*)d_out;

    __half *xhi, *aoh, *wh, *woh;
    __half *qah, *kah, *vah;
    float* bqkv;
    cudaGetSymbolAddress((void**)&xhi, g_xhi);
    cudaGetSymbolAddress((void**)&aoh, g_aoh);
    cudaGetSymbolAddress((void**)&wh,  g_wh);
    cudaGetSymbolAddress((void**)&woh, g_woh);
    cudaGetSymbolAddress((void**)&bqkv, g_bqkv);
    cudaGetSymbolAddress((void**)&qah, g_qah);
    cudaGetSymbolAddress((void**)&kah, g_kah);
    cudaGetSymbolAddress((void**)&vah, g_vah);

    cudaFuncSetAttribute(gemm_qkv, cudaFuncAttributeMaxDynamicSharedMemorySize, QGEMM_SMEM);
    cudaFuncSetAttribute(gemm_wo, cudaFuncAttributeMaxDynamicSharedMemorySize, QGEMM_SMEM);
    cudaFuncSetAttribute(flash_attn_hmma, cudaFuncAttributeMaxDynamicSharedMemorySize, FA_SMEM);

    const int n4 = MROWS * DIM / 4;

    // feeders: 2 launches total
    convert_h<<<(n4 + 255) / 256, 256>>>(x, xhi, n4);
    weight_prep<<<10240 + (NQKV + 255) / 256, 256>>>(
        Wq, Wk, Wv, Wo, bq, bk, bv, wh, woh, bqkv);

    // fused QKV projection + rmsnorm + rope (q carries full 1/hd)
    gemm_qkv<<<dim3(NQKV / BN, MROWS / BM), 256, QGEMM_SMEM>>>(
        xhi, wh, bqkv, qns, kns, qah, kah, vah);

    // attention (HMMA, plain fp16)
    flash_attn_hmma<<<dim3(SEQ / 128, NH, BATCH), 256, FA_SMEM>>>(
        qah, kah, vah, aoh);

    // output projection (plain fp16)
    gemm_wo<<<dim3(DIM / BN, MROWS / BM), 256, QGEMM_SMEM>>>(
        aoh, woh, bo, out, DIM);
}

// round 15
// speedup vs baseline: 1.0615x; 1.0215x over previous
#include <cuda_runtime.h>
#include <cuda_fp16.h>
#include <cstdint>
#include <math.h>

#define BATCH 16
#define SEQ   512
#define DIM   2048
#define NH    16
#define NG    4
#define HD    128
#define MROWS (BATCH*SEQ)   // 8192
#define KVD   (NG*HD)       // 512
#define NQKV  (DIM + 2*KVD) // 3072

// ---------------------------------------------------------------------------
// scratch (device globals — no allocation allowed)
// ---------------------------------------------------------------------------
__device__ __half g_xhi[(size_t)MROWS * DIM];
__device__ __half g_aoh[(size_t)MROWS * DIM];   // attn out fp16 (b,s,H,hd)
__device__ __half g_wh[(size_t)NQKV * DIM];     // [Wq^T; Wk^T; Wv^T] fp16
__device__ __half g_woh[(size_t)DIM * DIM];     // Wo^T fp16
__device__ float  g_bqkv[NQKV];                 // [bq; bk; bv]

// attention operand buffers, (b, head, s, hd) layout, plain fp16
__device__ __half g_qah[(size_t)MROWS * DIM];
__device__ __half g_kah[(size_t)MROWS * KVD];
__device__ __half g_vah[(size_t)MROWS * KVD];

// ---------------------------------------------------------------------------
// helpers
// ---------------------------------------------------------------------------
__device__ __forceinline__ uint32_t smem_to_u32(const void* p) {
    uint32_t a;
    asm("{ .reg .u64 t; cvta.to.shared.u64 t, %1; cvt.u32.u64 %0, t; }" : "=r"(a) : "l"(p));
    return a;
}
#define SMEM_SWIZZLE_128B(bo) ((bo) ^ (((bo) >> 3) & 0x70))

__device__ __forceinline__ void cp16(uint32_t s, const void* g) {
    asm volatile("cp.async.cg.shared.global [%0], [%1], 16;" :: "r"(s), "l"(g) : "memory");
}
#define CP_COMMIT() asm volatile("cp.async.commit_group;" ::: "memory")
#define CP_WAIT2()  asm volatile("cp.async.wait_group 2;" ::: "memory")
#define CP_WAIT1()  asm volatile("cp.async.wait_group 1;" ::: "memory")
#define CP_WAIT0()  asm volatile("cp.async.wait_group 0;" ::: "memory")
__device__ __forceinline__ void ldm4(uint32_t* r, uint32_t a) {
    asm volatile("ldmatrix.sync.aligned.m8n8.x4.shared.b16 {%0,%1,%2,%3}, [%4];"
                 : "=r"(r[0]), "=r"(r[1]), "=r"(r[2]), "=r"(r[3]) : "r"(a));
}
__device__ __forceinline__ void ldm4t(uint32_t* r, uint32_t a) {
    asm volatile("ldmatrix.sync.aligned.m8n8.x4.trans.shared.b16 {%0,%1,%2,%3}, [%4];"
                 : "=r"(r[0]), "=r"(r[1]), "=r"(r[2]), "=r"(r[3]) : "r"(a));
}
__device__ __forceinline__ void mma16816(float* d, const uint32_t* a, const uint32_t* b) {
    asm volatile(
        "mma.sync.aligned.m16n8k16.row.col.f32.f16.f16.f32 "
        "{%0,%1,%2,%3},{%4,%5,%6,%7},{%8,%9},{%0,%1,%2,%3};"
        : "+f"(d[0]), "+f"(d[1]), "+f"(d[2]), "+f"(d[3])
        : "r"(a[0]), "r"(a[1]), "r"(a[2]), "r"(a[3]), "r"(b[0]), "r"(b[1]));
}
__device__ __forceinline__ uint32_t pk2h(float a, float b) {
    __half2 h = __floats2half2_rn(a, b);
    return *reinterpret_cast<uint32_t*>(&h);
}

// ---------------------------------------------------------------------------
// convert fp32 -> fp16
// ---------------------------------------------------------------------------
__global__ __launch_bounds__(256) void convert_h(
    const float* __restrict__ in, __half* __restrict__ hi, int n4)
{
    int i = blockIdx.x * 256 + threadIdx.x;
    if (i >= n4) return;
    float4 v = ((const float4*)in)[i];
    uint2 ph;
    ph.x = pk2h(v.x, v.y); ph.y = pk2h(v.z, v.w);
    ((uint2*)hi)[i] = ph;
}

// ---------------------------------------------------------------------------
// Fused weight prep (one launch): transpose+convert Wq/Wk/Wv/Wo + bias concat
// ---------------------------------------------------------------------------
__global__ __launch_bounds__(256) void weight_prep(
    const float* __restrict__ Wq, const float* __restrict__ Wk,
    const float* __restrict__ Wv, const float* __restrict__ Wo,
    const float* __restrict__ bq, const float* __restrict__ bk,
    const float* __restrict__ bv,
    __half* __restrict__ wh, __half* __restrict__ woh,
    float* __restrict__ bqkv)
{
    int id = blockIdx.x;
    if (id >= 10240) {   // bias concat blocks
        int i = (id - 10240) * 256 + threadIdx.x;
        if (i < DIM) bqkv[i] = bq[i];
        else if (i < DIM + KVD) bqkv[i] = bk[i - DIM];
        else if (i < NQKV) bqkv[i] = bv[i - DIM - KVD];
        return;
    }

    const float* W;
    __half* T;
    int N, nb, base;
    if (id < 4096)      { W = Wq; T = wh;                              N = DIM; nb = 64; base = 0; }
    else if (id < 5120) { W = Wk; T = wh + (size_t)DIM * DIM;          N = KVD; nb = 16; base = 4096; }
    else if (id < 6144) { W = Wv; T = wh + (size_t)(DIM + KVD) * DIM;  N = KVD; nb = 16; base = 5120; }
    else                { W = Wo; T = woh;                             N = DIM; nb = 64; base = 6144; }
    int lid = id - base;
    int n0 = (lid % nb) * 32;
    int k0 = (lid / nb) * 32;

    __shared__ float tile[32][33];
    int tx = threadIdx.x & 31, ty = threadIdx.x >> 5;
    #pragma unroll
    for (int j = ty; j < 32; j += 8)
        tile[j][tx] = W[(size_t)(k0 + j) * N + n0 + tx];
    __syncthreads();
    #pragma unroll
    for (int j = ty; j < 32; j += 8)
        T[(size_t)(n0 + j) * DIM + k0 + tx] = __float2half_rn(tile[tx][j]);
}

// ---------------------------------------------------------------------------
// tile config — plain fp16 GEMM, stage = AH 16K + BH 16K, 3-stage
// ---------------------------------------------------------------------------
#define BM 128
#define BN 128
#define BK 64
#define NCH (DIM / BK)   // 32
#define QSTG_BYTES 32768
#define Q_OFF_AH 0
#define Q_OFF_BH 16384
#define QGEMM_SMEM (3 * QSTG_BYTES)   // 98304

// ---------------------------------------------------------------------------
// Fused QKV GEMM + RMSNorm + RoPE epilogue. Plain fp16; 2 CTAs/SM.
// ---------------------------------------------------------------------------
__global__ __launch_bounds__(256, 2) void gemm_qkv(
    const __half* __restrict__ Ahg, const __half* __restrict__ Bhg,
    const float* __restrict__ bias,
    const float* __restrict__ qns, const float* __restrict__ kns,
    __half* __restrict__ qah, __half* __restrict__ kah,
    __half* __restrict__ vah)
{
    extern __shared__ char sm[];
    uint32_t sb = smem_to_u32(sm);
    int tid = threadIdx.x, lane = tid & 31, wid = tid >> 5;
    int wm = wid & 1, wn = wid >> 1;
    int bx = blockIdx.x * BN, by = blockIdx.y * BM;

    auto load_stage = [&](int s, int kt) {
        int k0 = kt * BK;
        uint32_t base = sb + s * QSTG_BYTES;
        #pragma unroll
        for (int t = 0; t < 4; t++) {
            int idx = tid + t * 256;
            int r = idx >> 3, c16 = idx & 7;
            uint32_t swz = SMEM_SWIZZLE_128B((uint32_t)(r * 128 + c16 * 16));
            cp16(base + Q_OFF_AH + swz, Ahg + (size_t)(by + r) * DIM + k0 + c16 * 8);
            cp16(base + Q_OFF_BH + swz, Bhg + (size_t)(bx + r) * DIM + k0 + c16 * 8);
        }
    };

    float d[4][4][4];
    #pragma unroll
    for (int i = 0; i < 4; i++)
        #pragma unroll
        for (int j = 0; j < 4; j++)
            #pragma unroll
            for (int q = 0; q < 4; q++) d[i][j][q] = 0.f;

    load_stage(0, 0); CP_COMMIT();
    load_stage(1, 1); CP_COMMIT();
    load_stage(2, 2); CP_COMMIT();

    for (int kt = 0; kt < NCH; kt++) {
        CP_WAIT2();
        __syncthreads();

        int s = kt % 3;
        uint32_t base = sb + s * QSTG_BYTES;
        int arow = wm * 64 + (lane & 15);
        int bro  = wn * 32 + (lane & 7) + ((lane >> 4) << 3);
        int bkh  = ((lane >> 3) & 1) << 3;

        #pragma unroll
        for (int ks = 0; ks < 4; ks++) {
            int acol = ks * 16 + ((lane >> 4) << 3);
            uint32_t ah[4][4], bh[4][2];
            #pragma unroll
            for (int mf = 0; mf < 4; mf++) {
                uint32_t off = SMEM_SWIZZLE_128B(
                    (uint32_t)((arow + mf * 16) * 128 + acol * 2));
                ldm4(ah[mf], base + Q_OFF_AH + off);
            }
            #pragma unroll
            for (int j2 = 0; j2 < 2; j2++) {
                uint32_t off = SMEM_SWIZZLE_128B(
                    (uint32_t)((bro + j2 * 16) * 128 + (ks * 16 + bkh) * 2));
                uint32_t r[4];
                ldm4(r, base + Q_OFF_BH + off);
                bh[j2 * 2][0] = r[0]; bh[j2 * 2][1] = r[1];
                bh[j2 * 2 + 1][0] = r[2]; bh[j2 * 2 + 1][1] = r[3];
            }
            #pragma unroll
            for (int mf = 0; mf < 4; mf++)
                #pragma unroll
                for (int nf = 0; nf < 4; nf++)
                    mma16816(d[mf][nf], ah[mf], bh[nf]);
        }
        __syncthreads();

        if (kt + 3 < NCH) load_stage(s, kt + 3);
        CP_COMMIT();
    }

    // ---------------- fused epilogue ----------------
    int hb = blockIdx.x;             // 0..23
    bool needs_norm = (hb < 20);     // q and k blocks

    int c0 = wn * 32 + (lane & 3) * 2;
    #pragma unroll
    for (int mf = 0; mf < 4; mf++)
        #pragma unroll
        for (int nf = 0; nf < 4; nf++) {
            int c = c0 + nf * 8;
            float b0 = bias[bx + c], b1 = bias[bx + c + 1];
            d[mf][nf][0] += b0; d[mf][nf][1] += b1;
            d[mf][nf][2] += b0; d[mf][nf][3] += b1;
        }

    float* ss = (float*)sm;          // [128][4] partial row sums
    __syncthreads();

    if (needs_norm) {
        #pragma unroll
        for (int mf = 0; mf < 4; mf++) {
            float pA = 0.f, pB = 0.f;
            #pragma unroll
            for (int nf = 0; nf < 4; nf++) {
                pA += d[mf][nf][0] * d[mf][nf][0] + d[mf][nf][1] * d[mf][nf][1];
                pB += d[mf][nf][2] * d[mf][nf][2] + d[mf][nf][3] * d[mf][nf][3];
            }
            pA += __shfl_xor_sync(0xffffffffu, pA, 1);
            pA += __shfl_xor_sync(0xffffffffu, pA, 2);
            pB += __shfl_xor_sync(0xffffffffu, pB, 1);
            pB += __shfl_xor_sync(0xffffffffu, pB, 2);
            if ((lane & 3) == 0) {
                int lr = wm * 64 + mf * 16 + (lane >> 2);
                ss[lr * 4 + wn] = pA;
                ss[(lr + 8) * 4 + wn] = pB;
            }
        }
    }
    __syncthreads();

    const float* nsc = (hb < 16) ? qns : kns;
    float esc = (hb < 16) ? (1.0f / (float)HD) : 1.0f;
    __half* oph;
    int headmul;
    if (hb < 16)      { oph = qah; headmul = NH; }
    else if (hb < 20) { oph = kah; headmul = NG; }
    else              { oph = vah; headmul = NG; }
    int head = (hb < 16) ? hb : ((hb < 20) ? hb - 16 : hb - 20);

    #pragma unroll
    for (int mf = 0; mf < 4; mf++) {
        int lr = wm * 64 + mf * 16 + (lane >> 2);
        int rowA = by + lr, rowB = rowA + 8;
        int posA = rowA & (SEQ - 1), posB = rowB & (SEQ - 1);
        int bA = rowA >> 9, bB = rowB >> 9;
        float rinvA = 1.f, rinvB = 1.f;
        if (needs_norm) {
            float sA = ss[lr * 4] + ss[lr * 4 + 1] + ss[lr * 4 + 2] + ss[lr * 4 + 3];
            float sB = ss[(lr + 8) * 4] + ss[(lr + 8) * 4 + 1] +
                       ss[(lr + 8) * 4 + 2] + ss[(lr + 8) * 4 + 3];
            rinvA = rsqrtf(sA * (1.0f / HD) + 1e-6f);
            rinvB = rsqrtf(sB * (1.0f / HD) + 1e-6f);
        }
        size_t obA = ((size_t)(bA * headmul + head) * SEQ + posA) * HD;
        size_t obB = ((size_t)(bB * headmul + head) * SEQ + posB) * HD;
        #pragma unroll
        for (int nf = 0; nf < 4; nf++) {
            int c = c0 + nf * 8;
            if (needs_norm) {
                float sc0 = nsc[c], sc1 = nsc[c + 1];
                float invf = __expf(-(float)(c >> 1) * (9.210340371976184f / 64.0f));
                float snA, csA, snB, csB;
                __sincosf((float)posA * invf, &snA, &csA);
                __sincosf((float)posB * invf, &snB, &csB);
                float xA1 = d[mf][nf][0] * rinvA * sc0;
                float xA2 = d[mf][nf][1] * rinvA * sc1;
                float xB1 = d[mf][nf][2] * rinvB * sc0;
                float xB2 = d[mf][nf][3] * rinvB * sc1;
                *(__half2*)&oph[obA + c] = __floats2half2_rn(
                    (xA1 * csA - xA2 * snA) * esc, (xA1 * snA + xA2 * csA) * esc);
                *(__half2*)&oph[obB + c] = __floats2half2_rn(
                    (xB1 * csB - xB2 * snB) * esc, (xB1 * snB + xB2 * csB) * esc);
            } else {
                *(__half2*)&vah[obA + c] = __floats2half2_rn(d[mf][nf][0], d[mf][nf][1]);
                *(__half2*)&vah[obB + c] = __floats2half2_rn(d[mf][nf][2], d[mf][nf][3]);
            }
        }
    }
}

// ---------------------------------------------------------------------------
// Wo GEMM: plain fp16 single-product, bias, fp32 output; 2 CTAs/SM.
// ---------------------------------------------------------------------------
__global__ __launch_bounds__(256, 2) void gemm_wo(
    const __half* __restrict__ Ahg, const __half* __restrict__ Bhg,
    const float* __restrict__ bias, float* __restrict__ C, int N)
{
    extern __shared__ char sm[];
    uint32_t sb = smem_to_u32(sm);
    int tid = threadIdx.x, lane = tid & 31, wid = tid >> 5;
    int wm = wid & 1, wn = wid >> 1;
    int bx = blockIdx.x * BN, by = blockIdx.y * BM;

    auto load_stage = [&](int s, int kt) {
        int k0 = kt * BK;
        uint32_t base = sb + s * QSTG_BYTES;
        #pragma unroll
        for (int t = 0; t < 4; t++) {
            int idx = tid + t * 256;
            int r = idx >> 3, c16 = idx & 7;
            uint32_t swz = SMEM_SWIZZLE_128B((uint32_t)(r * 128 + c16 * 16));
            cp16(base + Q_OFF_AH + swz, Ahg + (size_t)(by + r) * DIM + k0 + c16 * 8);
            cp16(base + Q_OFF_BH + swz, Bhg + (size_t)(bx + r) * DIM + k0 + c16 * 8);
        }
    };

    float d[4][4][4];
    #pragma unroll
    for (int i = 0; i < 4; i++)
        #pragma unroll
        for (int j = 0; j < 4; j++)
            #pragma unroll
            for (int q = 0; q < 4; q++) d[i][j][q] = 0.f;

    load_stage(0, 0); CP_COMMIT();
    load_stage(1, 1); CP_COMMIT();
    load_stage(2, 2); CP_COMMIT();

    for (int kt = 0; kt < NCH; kt++) {
        CP_WAIT2();
        __syncthreads();

        int s = kt % 3;
        uint32_t base = sb + s * QSTG_BYTES;
        int arow = wm * 64 + (lane & 15);
        int bro  = wn * 32 + (lane & 7) + ((lane >> 4) << 3);
        int bkh  = ((lane >> 3) & 1) << 3;

        #pragma unroll
        for (int ks = 0; ks < 4; ks++) {
            int acol = ks * 16 + ((lane >> 4) << 3);
            uint32_t ah[4][4], bh[4][2];
            #pragma unroll
            for (int mf = 0; mf < 4; mf++) {
                uint32_t off = SMEM_SWIZZLE_128B(
                    (uint32_t)((arow + mf * 16) * 128 + acol * 2));
                ldm4(ah[mf], base + Q_OFF_AH + off);
            }
            #pragma unroll
            for (int j2 = 0; j2 < 2; j2++) {
                uint32_t off = SMEM_SWIZZLE_128B(
                    (uint32_t)((bro + j2 * 16) * 128 + (ks * 16 + bkh) * 2));
                uint32_t r[4];
                ldm4(r, base + Q_OFF_BH + off);
                bh[j2 * 2][0] = r[0]; bh[j2 * 2][1] = r[1];
                bh[j2 * 2 + 1][0] = r[2]; bh[j2 * 2 + 1][1] = r[3];
            }
            #pragma unroll
            for (int mf = 0; mf < 4; mf++)
                #pragma unroll
                for (int nf = 0; nf < 4; nf++)
                    mma16816(d[mf][nf], ah[mf], bh[nf]);
        }
        __syncthreads();

        if (kt + 3 < NCH) load_stage(s, kt + 3);
        CP_COMMIT();
    }

    int row0 = by + wm * 64 + (lane >> 2);
    int col0 = bx + wn * 32 + (lane & 3) * 2;
    #pragma unroll
    for (int mf = 0; mf < 4; mf++)
        #pragma unroll
        for (int nf = 0; nf < 4; nf++) {
            int r = row0 + mf * 16;
            int c = col0 + nf * 8;
            float b0 = bias[c], b1 = bias[c + 1];
            float2 v0 = make_float2(d[mf][nf][0] + b0, d[mf][nf][1] + b1);
            float2 v1 = make_float2(d[mf][nf][2] + b0, d[mf][nf][3] + b1);
            *(float2*)&C[(size_t)r * N + c] = v0;
            *(float2*)&C[(size_t)(r + 8) * N + c] = v1;
        }
}

// ---------------------------------------------------------------------------
// HMMA flash attention. BR=64, 4 warps, 2-stage K/V pipeline, 2 CTAs/SM.
// smem: Q 16KB + 2 x (K 16K + V 16K) = 80KB
// ---------------------------------------------------------------------------
#define FA_STG 32768
#define FA_SMEM (16384 + 2 * FA_STG)   // 81920

__global__ __launch_bounds__(128, 2) void flash_attn_hmma(
    const __half* __restrict__ qh, const __half* __restrict__ kh,
    const __half* __restrict__ vh, __half* __restrict__ aoh)
{
    extern __shared__ char sm[];
    uint32_t sb = smem_to_u32(sm);
    int qb = (gridDim.x - 1) - blockIdx.x;   // heavy tiles first
    int h = blockIdx.y, b = blockIdx.z;
    int g = h >> 2;
    int tid = threadIdx.x, lane = tid & 31, wid = tid >> 5;   // wid 0..3

    const size_t qbase  = ((size_t)(b * NH + h) * SEQ + qb * 64) * HD;
    const size_t kvbase = ((size_t)(b * NG + g) * SEQ) * HD;

    const uint32_t QH = sb;

    auto load_q = [&]() {
        #pragma unroll
        for (int t = 0; t < 8; t++) {
            int idx = tid + t * 128;
            int r = idx >> 4, c16 = idx & 15;          // 64 rows x 16 units
            uint32_t off = (uint32_t)((c16 >> 3) * 8192) +
                           SMEM_SWIZZLE_128B((uint32_t)(r * 128 + (c16 & 7) * 16));
            cp16(QH + off, qh + qbase + (size_t)r * HD + c16 * 8);
        }
    };
    auto load_kv = [&](int s, int kt) {
        uint32_t base = sb + 16384 + s * FA_STG;
        size_t kb = kvbase + (size_t)kt * 64 * HD;
        #pragma unroll
        for (int t = 0; t < 8; t++) {
            int idx = tid + t * 128;
            int r = idx >> 4, c16 = idx & 15;
            uint32_t off = (uint32_t)((c16 >> 3) * 8192) +
                           SMEM_SWIZZLE_128B((uint32_t)(r * 128 + (c16 & 7) * 16));
            size_t go = kb + (size_t)r * HD + c16 * 8;
            cp16(base + off,         kh + go);
            cp16(base + 16384 + off, vh + go);
        }
    };

    int nkt = qb + 1;
    load_q();
    load_kv(0, 0);
    CP_COMMIT();
    if (1 < nkt) load_kv(1, 1);
    CP_COMMIT();

    float o[16][4];
    #pragma unroll
    for (int i = 0; i < 16; i++)
        #pragma unroll
        for (int j = 0; j < 4; j++) o[i][j] = 0.f;
    float mA = -1e30f, mB = -1e30f, lA = 0.f, lB = 0.f;

    int row0 = wid * 16;
    int sq = qb * 64 + row0;

    for (int kt = 0; kt < nkt; kt++) {
        if (kt < nkt - 1) CP_WAIT1(); else CP_WAIT0();
        __syncthreads();

        int st = kt & 1;
        uint32_t KHb = sb + 16384 + st * FA_STG;
        uint32_t VHb = KHb + 16384;

        {
            float sc[8][4];
            #pragma unroll
            for (int i = 0; i < 8; i++)
                #pragma unroll
                for (int j = 0; j < 4; j++) sc[i][j] = 0.f;

            int aro  = row0 + (lane & 15);
            int kro  = (lane & 7) + ((lane >> 4) << 3);
            int bkh  = ((lane >> 3) & 1) << 3;

            // S = Q K^T
            #pragma unroll
            for (int ks = 0; ks < 8; ks++) {
                int chk  = ks >> 2;
                int acol = (ks & 3) * 16 + ((lane >> 4) << 3);
                uint32_t aoff = (uint32_t)(chk * 8192) +
                                SMEM_SWIZZLE_128B((uint32_t)(aro * 128 + acol * 2));
                uint32_t ah[4];
                ldm4(ah, QH + aoff);

                int bcol = (ks & 3) * 16 + bkh;
                uint32_t bh[8][2];
                #pragma unroll
                for (int j2 = 0; j2 < 4; j2++) {
                    uint32_t boff = (uint32_t)(chk * 8192) +
                        SMEM_SWIZZLE_128B((uint32_t)((j2 * 16 + kro) * 128 + bcol * 2));
                    uint32_t r[4];
                    ldm4(r, KHb + boff);
                    bh[2*j2][0] = r[0]; bh[2*j2][1] = r[1];
                    bh[2*j2+1][0] = r[2]; bh[2*j2+1][1] = r[3];
                }
                #pragma unroll
                for (int nf = 0; nf < 8; nf++)
                    mma16816(sc[nf], ah, bh[nf]);
            }

            // causal mask (diagonal tile only: kt == qb)
            if (kt * 64 + 63 > sq) {
                int rA = sq + (lane >> 2), rB = rA + 8;
                #pragma unroll
                for (int nf = 0; nf < 8; nf++) {
                    int cbase = kt * 64 + nf * 8 + 2 * (lane & 3);
                    if (cbase     > rA) sc[nf][0] = -1e30f;
                    if (cbase + 1 > rA) sc[nf][1] = -1e30f;
                    if (cbase     > rB) sc[nf][2] = -1e30f;
                    if (cbase + 1 > rB) sc[nf][3] = -1e30f;
                }
            }

            float mtA = -1e30f, mtB = -1e30f;
            #pragma unroll
            for (int nf = 0; nf < 8; nf++) {
                mtA = fmaxf(mtA, fmaxf(sc[nf][0], sc[nf][1]));
                mtB = fmaxf(mtB, fmaxf(sc[nf][2], sc[nf][3]));
            }
            mtA = fmaxf(mtA, __shfl_xor_sync(0xffffffffu, mtA, 1));
            mtA = fmaxf(mtA, __shfl_xor_sync(0xffffffffu, mtA, 2));
            mtB = fmaxf(mtB, __shfl_xor_sync(0xffffffffu, mtB, 1));
            mtB = fmaxf(mtB, __shfl_xor_sync(0xffffffffu, mtB, 2));
            float nmA = fmaxf(mA, mtA), nmB = fmaxf(mB, mtB);
            float alA = __expf(mA - nmA), alB = __expf(mB - nmB);

            float suA = 0.f, suB = 0.f;
            #pragma unroll
            for (int nf = 0; nf < 8; nf++) {
                sc[nf][0] = __expf(sc[nf][0] - nmA); suA += sc[nf][0];
                sc[nf][1] = __expf(sc[nf][1] - nmA); suA += sc[nf][1];
                sc[nf][2] = __expf(sc[nf][2] - nmB); suB += sc[nf][2];
                sc[nf][3] = __expf(sc[nf][3] - nmB); suB += sc[nf][3];
            }
            suA += __shfl_xor_sync(0xffffffffu, suA, 1);
            suA += __shfl_xor_sync(0xffffffffu, suA, 2);
            suB += __shfl_xor_sync(0xffffffffu, suB, 1);
            suB += __shfl_xor_sync(0xffffffffu, suB, 2);
            lA = lA * alA + suA;
            lB = lB * alB + suB;
            mA = nmA; mB = nmB;
            #pragma unroll
            for (int nf = 0; nf < 16; nf++) {
                o[nf][0] *= alA; o[nf][1] *= alA;
                o[nf][2] *= alB; o[nf][3] *= alB;
            }

            // O += P V
            int vro = (lane & 7) + (((lane >> 3) & 1) << 3);
            int vch = (lane >> 4) << 3;
            #pragma unroll
            for (int kf = 0; kf < 4; kf++) {
                uint32_t aPh[4];
                aPh[0] = pk2h(sc[2*kf][0],   sc[2*kf][1]);
                aPh[1] = pk2h(sc[2*kf][2],   sc[2*kf][3]);
                aPh[2] = pk2h(sc[2*kf+1][0], sc[2*kf+1][1]);
                aPh[3] = pk2h(sc[2*kf+1][2], sc[2*kf+1][3]);
                #pragma unroll
                for (int j2 = 0; j2 < 8; j2++) {
                    int chk  = j2 >> 2;
                    int wcol = (j2 & 3) * 16 + vch;
                    uint32_t voff = (uint32_t)(chk * 8192) +
                        SMEM_SWIZZLE_128B((uint32_t)((kf * 16 + vro) * 128 + wcol * 2));
                    uint32_t rh[4];
                    ldm4t(rh, VHb + voff);
                    uint32_t bh0[2] = {rh[0], rh[1]}, bh1[2] = {rh[2], rh[3]};
                    mma16816(o[2*j2],   aPh, bh0);
                    mma16816(o[2*j2+1], aPh, bh1);
                }
            }
        }
        __syncthreads();

        if (kt + 2 < nkt) load_kv(kt & 1, kt + 2);
        CP_COMMIT();
    }

    float rlA = 1.0f / lA, rlB = 1.0f / lB;
    int sA = sq + (lane >> 2), sB = sA + 8;
    size_t oA = ((size_t)(b * SEQ + sA) * NH + h) * HD;
    size_t oB = ((size_t)(b * SEQ + sB) * NH + h) * HD;
    #pragma unroll
    for (int nf = 0; nf < 16; nf++) {
        int hd = nf * 8 + 2 * (lane & 3);
        *(__half2*)&aoh[oA + hd] = __floats2half2_rn(o[nf][0] * rlA, o[nf][1] * rlA);
        *(__half2*)&aoh[oB + hd] = __floats2half2_rn(o[nf][2] * rlB, o[nf][3] * rlB);
    }
}

// ---------------------------------------------------------------------------
extern "C" void kernel_launch(void* const* d_in, const int* in_sizes, int n_in,
                              void* d_out, int out_size)
{
    const float* x   = (const float*)d_in[0];
    const float* Wq  = (const float*)d_in[1];
    const float* bq  = (const float*)d_in[2];
    const float* Wk  = (const float*)d_in[3];
    const float* bk  = (const float*)d_in[4];
    const float* Wv  = (const float*)d_in[5];
    const float* bv  = (const float*)d_in[6];
    const float* Wo  = (const float*)d_in[7];
    const float* bo  = (const float*)d_in[8];
    const float* qns = (const float*)d_in[9];
    const float* kns = (const float*)d_in[10];
    float* out = (float*)d_out;

    __half *xhi, *aoh, *wh, *woh;
    __half *qah, *kah, *vah;
    float* bqkv;
    cudaGetSymbolAddress((void**)&xhi, g_xhi);
    cudaGetSymbolAddress((void**)&aoh, g_aoh);
    cudaGetSymbolAddress((void**)&wh,  g_wh);
    cudaGetSymbolAddress((void**)&woh, g_woh);
    cudaGetSymbolAddress((void**)&bqkv, g_bqkv);
    cudaGetSymbolAddress((void**)&qah, g_qah);
    cudaGetSymbolAddress((void**)&kah, g_kah);
    cudaGetSymbolAddress((void**)&vah, g_vah);

    cudaFuncSetAttribute(gemm_qkv, cudaFuncAttributeMaxDynamicSharedMemorySize, QGEMM_SMEM);
    cudaFuncSetAttribute(gemm_wo, cudaFuncAttributeMaxDynamicSharedMemorySize, QGEMM_SMEM);
    cudaFuncSetAttribute(flash_attn_hmma, cudaFuncAttributeMaxDynamicSharedMemorySize, FA_SMEM);

    const int n4 = MROWS * DIM / 4;

    // feeders: 2 launches total
    convert_h<<<(n4 + 255) / 256, 256>>>(x, xhi, n4);
    weight_prep<<<10240 + (NQKV + 255) / 256, 256>>>(
        Wq, Wk, Wv, Wo, bq, bk, bv, wh, woh, bqkv);

    // fused QKV projection + rmsnorm + rope (q carries full 1/hd)
    gemm_qkv<<<dim3(NQKV / BN, MROWS / BM), 256, QGEMM_SMEM>>>(
        xhi, wh, bqkv, qns, kns, qah, kah, vah);

    // attention (HMMA, plain fp16, BR=64, 2 CTAs/SM)
    flash_attn_hmma<<<dim3(SEQ / 64, NH, BATCH), 128, FA_SMEM>>>(
        qah, kah, vah, aoh);

    // output projection (plain fp16)
    gemm_wo<<<dim3(DIM / BN, MROWS / BM), 256, QGEMM_SMEM>>>(
        aoh, woh, bo, out, DIM);
}

// round 16
// speedup vs baseline: 1.0723x; 1.0102x over previous
#include <cuda_runtime.h>
#include <cuda_fp16.h>
#include <cstdint>
#include <math.h>

#define BATCH 16
#define SEQ   512
#define DIM   2048
#define NH    16
#define NG    4
#define HD    128
#define MROWS (BATCH*SEQ)   // 8192
#define KVD   (NG*HD)       // 512
#define NQKV  (DIM + 2*KVD) // 3072

// ---------------------------------------------------------------------------
// scratch (device globals — no allocation allowed)
// ---------------------------------------------------------------------------
__device__ __half g_xhi[(size_t)MROWS * DIM];
__device__ __half g_aoh[(size_t)MROWS * DIM];   // attn out fp16 (b,s,H,hd)
__device__ __half g_wh[(size_t)NQKV * DIM];     // [Wq^T; Wk^T; Wv^T] fp16
__device__ __half g_woh[(size_t)DIM * DIM];     // Wo^T fp16
__device__ float  g_bqkv[NQKV];                 // [bq; bk; bv]

// attention operand buffers, (b, head, s, hd) layout, plain fp16
__device__ __half g_qah[(size_t)MROWS * DIM];
__device__ __half g_kah[(size_t)MROWS * KVD];
__device__ __half g_vah[(size_t)MROWS * KVD];

// ---------------------------------------------------------------------------
// helpers
// ---------------------------------------------------------------------------
__device__ __forceinline__ uint32_t smem_to_u32(const void* p) {
    uint32_t a;
    asm("{ .reg .u64 t; cvta.to.shared.u64 t, %1; cvt.u32.u64 %0, t; }" : "=r"(a) : "l"(p));
    return a;
}
#define SMEM_SWIZZLE_128B(bo) ((bo) ^ (((bo) >> 3) & 0x70))

__device__ __forceinline__ void cp16(uint32_t s, const void* g) {
    asm volatile("cp.async.cg.shared.global [%0], [%1], 16;" :: "r"(s), "l"(g) : "memory");
}
#define CP_COMMIT() asm volatile("cp.async.commit_group;" ::: "memory")
#define CP_WAIT2()  asm volatile("cp.async.wait_group 2;" ::: "memory")
#define CP_WAIT1()  asm volatile("cp.async.wait_group 1;" ::: "memory")
#define CP_WAIT0()  asm volatile("cp.async.wait_group 0;" ::: "memory")
__device__ __forceinline__ void ldm4(uint32_t* r, uint32_t a) {
    asm volatile("ldmatrix.sync.aligned.m8n8.x4.shared.b16 {%0,%1,%2,%3}, [%4];"
                 : "=r"(r[0]), "=r"(r[1]), "=r"(r[2]), "=r"(r[3]) : "r"(a));
}
__device__ __forceinline__ void ldm4t(uint32_t* r, uint32_t a) {
    asm volatile("ldmatrix.sync.aligned.m8n8.x4.trans.shared.b16 {%0,%1,%2,%3}, [%4];"
                 : "=r"(r[0]), "=r"(r[1]), "=r"(r[2]), "=r"(r[3]) : "r"(a));
}
__device__ __forceinline__ void mma16816(float* d, const uint32_t* a, const uint32_t* b) {
    asm volatile(
        "mma.sync.aligned.m16n8k16.row.col.f32.f16.f16.f32 "
        "{%0,%1,%2,%3},{%4,%5,%6,%7},{%8,%9},{%0,%1,%2,%3};"
        : "+f"(d[0]), "+f"(d[1]), "+f"(d[2]), "+f"(d[3])
        : "r"(a[0]), "r"(a[1]), "r"(a[2]), "r"(a[3]), "r"(b[0]), "r"(b[1]));
}
__device__ __forceinline__ uint32_t pk2h(float a, float b) {
    __half2 h = __floats2half2_rn(a, b);
    return *reinterpret_cast<uint32_t*>(&h);
}

// ---------------------------------------------------------------------------
// Fused prep (ONE launch): x fp32->fp16, weight transpose+convert, bias concat
// Block map: [0,16384)        convert x
//            [16384,20480)    Wq   [20480,21504) Wk   [21504,22528) Wv
//            [22528,26624)    Wo
//            [26624,26636)    bias concat
// ---------------------------------------------------------------------------
#define PREP_XBLK 16384
#define PREP_WBLK 10240
#define PREP_TOTAL (PREP_XBLK + PREP_WBLK + (NQKV + 255) / 256)

__global__ __launch_bounds__(256) void prep_all(
    const float* __restrict__ x,
    const float* __restrict__ Wq, const float* __restrict__ Wk,
    const float* __restrict__ Wv, const float* __restrict__ Wo,
    const float* __restrict__ bq, const float* __restrict__ bk,
    const float* __restrict__ bv,
    __half* __restrict__ xhi,
    __half* __restrict__ wh, __half* __restrict__ woh,
    float* __restrict__ bqkv)
{
    int id = blockIdx.x;
    if (id < PREP_XBLK) {            // x convert (float4 per thread)
        int i = id * 256 + threadIdx.x;
        float4 v = ((const float4*)x)[i];
        uint2 ph;
        ph.x = pk2h(v.x, v.y); ph.y = pk2h(v.z, v.w);
        ((uint2*)xhi)[i] = ph;
        return;
    }
    id -= PREP_XBLK;
    if (id >= PREP_WBLK) {           // bias concat
        int i = (id - PREP_WBLK) * 256 + threadIdx.x;
        if (i < DIM) bqkv[i] = bq[i];
        else if (i < DIM + KVD) bqkv[i] = bk[i - DIM];
        else if (i < NQKV) bqkv[i] = bv[i - DIM - KVD];
        return;
    }

    const float* W;
    __half* T;
    int N, nb, base;
    if (id < 4096)      { W = Wq; T = wh;                              N = DIM; nb = 64; base = 0; }
    else if (id < 5120) { W = Wk; T = wh + (size_t)DIM * DIM;          N = KVD; nb = 16; base = 4096; }
    else if (id < 6144) { W = Wv; T = wh + (size_t)(DIM + KVD) * DIM;  N = KVD; nb = 16; base = 5120; }
    else                { W = Wo; T = woh;                             N = DIM; nb = 64; base = 6144; }
    int lid = id - base;
    int n0 = (lid % nb) * 32;
    int k0 = (lid / nb) * 32;

    __shared__ float tile[32][33];
    int tx = threadIdx.x & 31, ty = threadIdx.x >> 5;
    #pragma unroll
    for (int j = ty; j < 32; j += 8)
        tile[j][tx] = W[(size_t)(k0 + j) * N + n0 + tx];
    __syncthreads();
    #pragma unroll
    for (int j = ty; j < 32; j += 8)
        T[(size_t)(n0 + j) * DIM + k0 + tx] = __float2half_rn(tile[tx][j]);
}

// ---------------------------------------------------------------------------
// tile config — plain fp16 GEMM, stage = AH 16K + BH 16K, 3-stage
// ---------------------------------------------------------------------------
#define BM 128
#define BN 128
#define BK 64
#define NCH (DIM / BK)   // 32
#define QSTG_BYTES 32768
#define Q_OFF_AH 0
#define Q_OFF_BH 16384
#define QGEMM_SMEM (3 * QSTG_BYTES)   // 98304

// ---------------------------------------------------------------------------
// Fused QKV GEMM + RMSNorm + RoPE epilogue. Plain fp16; 2 CTAs/SM.
// ---------------------------------------------------------------------------
__global__ __launch_bounds__(256, 2) void gemm_qkv(
    const __half* __restrict__ Ahg, const __half* __restrict__ Bhg,
    const float* __restrict__ bias,
    const float* __restrict__ qns, const float* __restrict__ kns,
    __half* __restrict__ qah, __half* __restrict__ kah,
    __half* __restrict__ vah)
{
    extern __shared__ char sm[];
    uint32_t sb = smem_to_u32(sm);
    int tid = threadIdx.x, lane = tid & 31, wid = tid >> 5;
    int wm = wid & 1, wn = wid >> 1;
    int bx = blockIdx.x * BN, by = blockIdx.y * BM;

    auto load_stage = [&](int s, int kt) {
        int k0 = kt * BK;
        uint32_t base = sb + s * QSTG_BYTES;
        #pragma unroll
        for (int t = 0; t < 4; t++) {
            int idx = tid + t * 256;
            int r = idx >> 3, c16 = idx & 7;
            uint32_t swz = SMEM_SWIZZLE_128B((uint32_t)(r * 128 + c16 * 16));
            cp16(base + Q_OFF_AH + swz, Ahg + (size_t)(by + r) * DIM + k0 + c16 * 8);
            cp16(base + Q_OFF_BH + swz, Bhg + (size_t)(bx + r) * DIM + k0 + c16 * 8);
        }
    };

    float d[4][4][4];
    #pragma unroll
    for (int i = 0; i < 4; i++)
        #pragma unroll
        for (int j = 0; j < 4; j++)
            #pragma unroll
            for (int q = 0; q < 4; q++) d[i][j][q] = 0.f;

    load_stage(0, 0); CP_COMMIT();
    load_stage(1, 1); CP_COMMIT();
    load_stage(2, 2); CP_COMMIT();

    for (int kt = 0; kt < NCH; kt++) {
        CP_WAIT2();
        __syncthreads();

        int s = kt % 3;
        uint32_t base = sb + s * QSTG_BYTES;
        int arow = wm * 64 + (lane & 15);
        int bro  = wn * 32 + (lane & 7) + ((lane >> 4) << 3);
        int bkh  = ((lane >> 3) & 1) << 3;

        #pragma unroll
        for (int ks = 0; ks < 4; ks++) {
            int acol = ks * 16 + ((lane >> 4) << 3);
            uint32_t ah[4][4], bh[4][2];
            #pragma unroll
            for (int mf = 0; mf < 4; mf++) {
                uint32_t off = SMEM_SWIZZLE_128B(
                    (uint32_t)((arow + mf * 16) * 128 + acol * 2));
                ldm4(ah[mf], base + Q_OFF_AH + off);
            }
            #pragma unroll
            for (int j2 = 0; j2 < 2; j2++) {
                uint32_t off = SMEM_SWIZZLE_128B(
                    (uint32_t)((bro + j2 * 16) * 128 + (ks * 16 + bkh) * 2));
                uint32_t r[4];
                ldm4(r, base + Q_OFF_BH + off);
                bh[j2 * 2][0] = r[0]; bh[j2 * 2][1] = r[1];
                bh[j2 * 2 + 1][0] = r[2]; bh[j2 * 2 + 1][1] = r[3];
            }
            #pragma unroll
            for (int mf = 0; mf < 4; mf++)
                #pragma unroll
                for (int nf = 0; nf < 4; nf++)
                    mma16816(d[mf][nf], ah[mf], bh[nf]);
        }
        __syncthreads();

        if (kt + 3 < NCH) load_stage(s, kt + 3);
        CP_COMMIT();
    }

    // ---------------- fused epilogue ----------------
    int hb = blockIdx.x;             // 0..23
    bool needs_norm = (hb < 20);     // q and k blocks

    int c0 = wn * 32 + (lane & 3) * 2;
    #pragma unroll
    for (int mf = 0; mf < 4; mf++)
        #pragma unroll
        for (int nf = 0; nf < 4; nf++) {
            int c = c0 + nf * 8;
            float b0 = bias[bx + c], b1 = bias[bx + c + 1];
            d[mf][nf][0] += b0; d[mf][nf][1] += b1;
            d[mf][nf][2] += b0; d[mf][nf][3] += b1;
        }

    float* ss = (float*)sm;          // [128][4] partial row sums
    __syncthreads();

    if (needs_norm) {
        #pragma unroll
        for (int mf = 0; mf < 4; mf++) {
            float pA = 0.f, pB = 0.f;
            #pragma unroll
            for (int nf = 0; nf < 4; nf++) {
                pA += d[mf][nf][0] * d[mf][nf][0] + d[mf][nf][1] * d[mf][nf][1];
                pB += d[mf][nf][2] * d[mf][nf][2] + d[mf][nf][3] * d[mf][nf][3];
            }
            pA += __shfl_xor_sync(0xffffffffu, pA, 1);
            pA += __shfl_xor_sync(0xffffffffu, pA, 2);
            pB += __shfl_xor_sync(0xffffffffu, pB, 1);
            pB += __shfl_xor_sync(0xffffffffu, pB, 2);
            if ((lane & 3) == 0) {
                int lr = wm * 64 + mf * 16 + (lane >> 2);
                ss[lr * 4 + wn] = pA;
                ss[(lr + 8) * 4 + wn] = pB;
            }
        }
    }
    __syncthreads();

    const float* nsc = (hb < 16) ? qns : kns;
    float esc = (hb < 16) ? (1.0f / (float)HD) : 1.0f;
    __half* oph;
    int headmul;
    if (hb < 16)      { oph = qah; headmul = NH; }
    else if (hb < 20) { oph = kah; headmul = NG; }
    else              { oph = vah; headmul = NG; }
    int head = (hb < 16) ? hb : ((hb < 20) ? hb - 16 : hb - 20);

    #pragma unroll
    for (int mf = 0; mf < 4; mf++) {
        int lr = wm * 64 + mf * 16 + (lane >> 2);
        int rowA = by + lr, rowB = rowA + 8;
        int posA = rowA & (SEQ - 1), posB = rowB & (SEQ - 1);
        int bA = rowA >> 9, bB = rowB >> 9;
        float rinvA = 1.f, rinvB = 1.f;
        if (needs_norm) {
            float sA = ss[lr * 4] + ss[lr * 4 + 1] + ss[lr * 4 + 2] + ss[lr * 4 + 3];
            float sB = ss[(lr + 8) * 4] + ss[(lr + 8) * 4 + 1] +
                       ss[(lr + 8) * 4 + 2] + ss[(lr + 8) * 4 + 3];
            rinvA = rsqrtf(sA * (1.0f / HD) + 1e-6f);
            rinvB = rsqrtf(sB * (1.0f / HD) + 1e-6f);
        }
        size_t obA = ((size_t)(bA * headmul + head) * SEQ + posA) * HD;
        size_t obB = ((size_t)(bB * headmul + head) * SEQ + posB) * HD;
        #pragma unroll
        for (int nf = 0; nf < 4; nf++) {
            int c = c0 + nf * 8;
            if (needs_norm) {
                float sc0 = nsc[c], sc1 = nsc[c + 1];
                float invf = __expf(-(float)(c >> 1) * (9.210340371976184f / 64.0f));
                float snA, csA, snB, csB;
                __sincosf((float)posA * invf, &snA, &csA);
                __sincosf((float)posB * invf, &snB, &csB);
                float xA1 = d[mf][nf][0] * rinvA * sc0;
                float xA2 = d[mf][nf][1] * rinvA * sc1;
                float xB1 = d[mf][nf][2] * rinvB * sc0;
                float xB2 = d[mf][nf][3] * rinvB * sc1;
                *(__half2*)&oph[obA + c] = __floats2half2_rn(
                    (xA1 * csA - xA2 * snA) * esc, (xA1 * snA + xA2 * csA) * esc);
                *(__half2*)&oph[obB + c] = __floats2half2_rn(
                    (xB1 * csB - xB2 * snB) * esc, (xB1 * snB + xB2 * csB) * esc);
            } else {
                *(__half2*)&vah[obA + c] = __floats2half2_rn(d[mf][nf][0], d[mf][nf][1]);
                *(__half2*)&vah[obB + c] = __floats2half2_rn(d[mf][nf][2], d[mf][nf][3]);
            }
        }
    }
}

// ---------------------------------------------------------------------------
// Wo GEMM: plain fp16 single-product, bias, fp32 output; 2 CTAs/SM.
// ---------------------------------------------------------------------------
__global__ __launch_bounds__(256, 2) void gemm_wo(
    const __half* __restrict__ Ahg, const __half* __restrict__ Bhg,
    const float* __restrict__ bias, float* __restrict__ C, int N)
{
    extern __shared__ char sm[];
    uint32_t sb = smem_to_u32(sm);
    int tid = threadIdx.x, lane = tid & 31, wid = tid >> 5;
    int wm = wid & 1, wn = wid >> 1;
    int bx = blockIdx.x * BN, by = blockIdx.y * BM;

    auto load_stage = [&](int s, int kt) {
        int k0 = kt * BK;
        uint32_t base = sb + s * QSTG_BYTES;
        #pragma unroll
        for (int t = 0; t < 4; t++) {
            int idx = tid + t * 256;
            int r = idx >> 3, c16 = idx & 7;
            uint32_t swz = SMEM_SWIZZLE_128B((uint32_t)(r * 128 + c16 * 16));
            cp16(base + Q_OFF_AH + swz, Ahg + (size_t)(by + r) * DIM + k0 + c16 * 8);
            cp16(base + Q_OFF_BH + swz, Bhg + (size_t)(bx + r) * DIM + k0 + c16 * 8);
        }
    };

    float d[4][4][4];
    #pragma unroll
    for (int i = 0; i < 4; i++)
        #pragma unroll
        for (int j = 0; j < 4; j++)
            #pragma unroll
            for (int q = 0; q < 4; q++) d[i][j][q] = 0.f;

    load_stage(0, 0); CP_COMMIT();
    load_stage(1, 1); CP_COMMIT();
    load_stage(2, 2); CP_COMMIT();

    for (int kt = 0; kt < NCH; kt++) {
        CP_WAIT2();
        __syncthreads();

        int s = kt % 3;
        uint32_t base = sb + s * QSTG_BYTES;
        int arow = wm * 64 + (lane & 15);
        int bro  = wn * 32 + (lane & 7) + ((lane >> 4) << 3);
        int bkh  = ((lane >> 3) & 1) << 3;

        #pragma unroll
        for (int ks = 0; ks < 4; ks++) {
            int acol = ks * 16 + ((lane >> 4) << 3);
            uint32_t ah[4][4], bh[4][2];
            #pragma unroll
            for (int mf = 0; mf < 4; mf++) {
                uint32_t off = SMEM_SWIZZLE_128B(
                    (uint32_t)((arow + mf * 16) * 128 + acol * 2));
                ldm4(ah[mf], base + Q_OFF_AH + off);
            }
            #pragma unroll
            for (int j2 = 0; j2 < 2; j2++) {
                uint32_t off = SMEM_SWIZZLE_128B(
                    (uint32_t)((bro + j2 * 16) * 128 + (ks * 16 + bkh) * 2));
                uint32_t r[4];
                ldm4(r, base + Q_OFF_BH + off);
                bh[j2 * 2][0] = r[0]; bh[j2 * 2][1] = r[1];
                bh[j2 * 2 + 1][0] = r[2]; bh[j2 * 2 + 1][1] = r[3];
            }
            #pragma unroll
            for (int mf = 0; mf < 4; mf++)
                #pragma unroll
                for (int nf = 0; nf < 4; nf++)
                    mma16816(d[mf][nf], ah[mf], bh[nf]);
        }
        __syncthreads();

        if (kt + 3 < NCH) load_stage(s, kt + 3);
        CP_COMMIT();
    }

    int row0 = by + wm * 64 + (lane >> 2);
    int col0 = bx + wn * 32 + (lane & 3) * 2;
    #pragma unroll
    for (int mf = 0; mf < 4; mf++)
        #pragma unroll
        for (int nf = 0; nf < 4; nf++) {
            int r = row0 + mf * 16;
            int c = col0 + nf * 8;
            float b0 = bias[c], b1 = bias[c + 1];
            float2 v0 = make_float2(d[mf][nf][0] + b0, d[mf][nf][1] + b1);
            float2 v1 = make_float2(d[mf][nf][2] + b0, d[mf][nf][3] + b1);
            *(float2*)&C[(size_t)r * N + c] = v0;
            *(float2*)&C[(size_t)(r + 8) * N + c] = v1;
        }
}

// ---------------------------------------------------------------------------
// HMMA flash attention. BR=64, 4 warps, 2-stage K/V pipeline, 2 CTAs/SM.
// Q fragments register-resident (loaded once). smem: 16KB + 2x32KB = 80KB
// ---------------------------------------------------------------------------
#define FA_STG 32768
#define FA_SMEM (16384 + 2 * FA_STG)   // 81920

__global__ __launch_bounds__(128, 2) void flash_attn_hmma(
    const __half* __restrict__ qh, const __half* __restrict__ kh,
    const __half* __restrict__ vh, __half* __restrict__ aoh)
{
    extern __shared__ char sm[];
    uint32_t sb = smem_to_u32(sm);
    int qb = (gridDim.x - 1) - blockIdx.x;   // heavy tiles first
    int h = blockIdx.y, b = blockIdx.z;
    int g = h >> 2;
    int tid = threadIdx.x, lane = tid & 31, wid = tid >> 5;   // wid 0..3

    const size_t qbase  = ((size_t)(b * NH + h) * SEQ + qb * 64) * HD;
    const size_t kvbase = ((size_t)(b * NG + g) * SEQ) * HD;

    const uint32_t QH = sb;

    auto load_q = [&]() {
        #pragma unroll
        for (int t = 0; t < 8; t++) {
            int idx = tid + t * 128;
            int r = idx >> 4, c16 = idx & 15;          // 64 rows x 16 units
            uint32_t off = (uint32_t)((c16 >> 3) * 8192) +
                           SMEM_SWIZZLE_128B((uint32_t)(r * 128 + (c16 & 7) * 16));
            cp16(QH + off, qh + qbase + (size_t)r * HD + c16 * 8);
        }
    };
    auto load_kv = [&](int s, int kt) {
        uint32_t base = sb + 16384 + s * FA_STG;
        size_t kb = kvbase + (size_t)kt * 64 * HD;
        #pragma unroll
        for (int t = 0; t < 8; t++) {
            int idx = tid + t * 128;
            int r = idx >> 4, c16 = idx & 15;
            uint32_t off = (uint32_t)((c16 >> 3) * 8192) +
                           SMEM_SWIZZLE_128B((uint32_t)(r * 128 + (c16 & 7) * 16));
            size_t go = kb + (size_t)r * HD + c16 * 8;
            cp16(base + off,         kh + go);
            cp16(base + 16384 + off, vh + go);
        }
    };

    int nkt = qb + 1;
    load_q();
    load_kv(0, 0);
    CP_COMMIT();
    if (1 < nkt) load_kv(1, 1);
    CP_COMMIT();

    // preload Q fragments (register-resident for the whole mainloop)
    CP_WAIT1();                       // group0 {Q, KV0} complete
    __syncthreads();
    int row0 = wid * 16;
    uint32_t qf[8][4];
    {
        int aro = row0 + (lane & 15);
        #pragma unroll
        for (int ks = 0; ks < 8; ks++) {
            int chk  = ks >> 2;
            int acol = (ks & 3) * 16 + ((lane >> 4) << 3);
            uint32_t aoff = (uint32_t)(chk * 8192) +
                            SMEM_SWIZZLE_128B((uint32_t)(aro * 128 + acol * 2));
            ldm4(qf[ks], QH + aoff);
        }
    }

    float o[16][4];
    #pragma unroll
    for (int i = 0; i < 16; i++)
        #pragma unroll
        for (int j = 0; j < 4; j++) o[i][j] = 0.f;
    float mA = -1e30f, mB = -1e30f, lA = 0.f, lB = 0.f;

    int sq = qb * 64 + row0;

    for (int kt = 0; kt < nkt; kt++) {
        if (kt < nkt - 1) CP_WAIT1(); else CP_WAIT0();
        __syncthreads();

        int st = kt & 1;
        uint32_t KHb = sb + 16384 + st * FA_STG;
        uint32_t VHb = KHb + 16384;

        {
            float sc[8][4];
            #pragma unroll
            for (int i = 0; i < 8; i++)
                #pragma unroll
                for (int j = 0; j < 4; j++) sc[i][j] = 0.f;

            int kro  = (lane & 7) + ((lane >> 4) << 3);
            int bkh  = ((lane >> 3) & 1) << 3;

            // S = Q K^T (Q fragments in registers)
            #pragma unroll
            for (int ks = 0; ks < 8; ks++) {
                int chk  = ks >> 2;
                int bcol = (ks & 3) * 16 + bkh;
                uint32_t bh[8][2];
                #pragma unroll
                for (int j2 = 0; j2 < 4; j2++) {
                    uint32_t boff = (uint32_t)(chk * 8192) +
                        SMEM_SWIZZLE_128B((uint32_t)((j2 * 16 + kro) * 128 + bcol * 2));
                    uint32_t r[4];
                    ldm4(r, KHb + boff);
                    bh[2*j2][0] = r[0]; bh[2*j2][1] = r[1];
                    bh[2*j2+1][0] = r[2]; bh[2*j2+1][1] = r[3];
                }
                #pragma unroll
                for (int nf = 0; nf < 8; nf++)
                    mma16816(sc[nf], qf[ks], bh[nf]);
            }

            // causal mask (diagonal tile only: kt == qb)
            if (kt * 64 + 63 > sq) {
                int rA = sq + (lane >> 2), rB = rA + 8;
                #pragma unroll
                for (int nf = 0; nf < 8; nf++) {
                    int cbase = kt * 64 + nf * 8 + 2 * (lane & 3);
                    if (cbase     > rA) sc[nf][0] = -1e30f;
                    if (cbase + 1 > rA) sc[nf][1] = -1e30f;
                    if (cbase     > rB) sc[nf][2] = -1e30f;
                    if (cbase + 1 > rB) sc[nf][3] = -1e30f;
                }
            }

            float mtA = -1e30f, mtB = -1e30f;
            #pragma unroll
            for (int nf = 0; nf < 8; nf++) {
                mtA = fmaxf(mtA, fmaxf(sc[nf][0], sc[nf][1]));
                mtB = fmaxf(mtB, fmaxf(sc[nf][2], sc[nf][3]));
            }
            mtA = fmaxf(mtA, __shfl_xor_sync(0xffffffffu, mtA, 1));
            mtA = fmaxf(mtA, __shfl_xor_sync(0xffffffffu, mtA, 2));
            mtB = fmaxf(mtB, __shfl_xor_sync(0xffffffffu, mtB, 1));
            mtB = fmaxf(mtB, __shfl_xor_sync(0xffffffffu, mtB, 2));
            float nmA = fmaxf(mA, mtA), nmB = fmaxf(mB, mtB);
            float alA = __expf(mA - nmA), alB = __expf(mB - nmB);

            float suA = 0.f, suB = 0.f;
            #pragma unroll
            for (int nf = 0; nf < 8; nf++) {
                sc[nf][0] = __expf(sc[nf][0] - nmA); suA += sc[nf][0];
                sc[nf][1] = __expf(sc[nf][1] - nmA); suA += sc[nf][1];
                sc[nf][2] = __expf(sc[nf][2] - nmB); suB += sc[nf][2];
                sc[nf][3] = __expf(sc[nf][3] - nmB); suB += sc[nf][3];
            }
            suA += __shfl_xor_sync(0xffffffffu, suA, 1);
            suA += __shfl_xor_sync(0xffffffffu, suA, 2);
            suB += __shfl_xor_sync(0xffffffffu, suB, 1);
            suB += __shfl_xor_sync(0xffffffffu, suB, 2);
            lA = lA * alA + suA;
            lB = lB * alB + suB;
            mA = nmA; mB = nmB;
            #pragma unroll
            for (int nf = 0; nf < 16; nf++) {
                o[nf][0] *= alA; o[nf][1] *= alA;
                o[nf][2] *= alB; o[nf][3] *= alB;
            }

            // O += P V
            int vro = (lane & 7) + (((lane >> 3) & 1) << 3);
            int vch = (lane >> 4) << 3;
            #pragma unroll
            for (int kf = 0; kf < 4; kf++) {
                uint32_t aPh[4];
                aPh[0] = pk2h(sc[2*kf][0],   sc[2*kf][1]);
                aPh[1] = pk2h(sc[2*kf][2],   sc[2*kf][3]);
                aPh[2] = pk2h(sc[2*kf+1][0], sc[2*kf+1][1]);
                aPh[3] = pk2h(sc[2*kf+1][2], sc[2*kf+1][3]);
                #pragma unroll
                for (int j2 = 0; j2 < 8; j2++) {
                    int chk  = j2 >> 2;
                    int wcol = (j2 & 3) * 16 + vch;
                    uint32_t voff = (uint32_t)(chk * 8192) +
                        SMEM_SWIZZLE_128B((uint32_t)((kf * 16 + vro) * 128 + wcol * 2));
                    uint32_t rh[4];
                    ldm4t(rh, VHb + voff);
                    uint32_t bh0[2] = {rh[0], rh[1]}, bh1[2] = {rh[2], rh[3]};
                    mma16816(o[2*j2],   aPh, bh0);
                    mma16816(o[2*j2+1], aPh, bh1);
                }
            }
        }
        __syncthreads();

        if (kt + 2 < nkt) load_kv(kt & 1, kt + 2);
        CP_COMMIT();
    }

    float rlA = 1.0f / lA, rlB = 1.0f / lB;
    int sA = sq + (lane >> 2), sB = sA + 8;
    size_t oA = ((size_t)(b * SEQ + sA) * NH + h) * HD;
    size_t oB = ((size_t)(b * SEQ + sB) * NH + h) * HD;
    #pragma unroll
    for (int nf = 0; nf < 16; nf++) {
        int hd = nf * 8 + 2 * (lane & 3);
        *(__half2*)&aoh[oA + hd] = __floats2half2_rn(o[nf][0] * rlA, o[nf][1] * rlA);
        *(__half2*)&aoh[oB + hd] = __floats2half2_rn(o[nf][2] * rlB, o[nf][3] * rlB);
    }
}

// ---------------------------------------------------------------------------
extern "C" void kernel_launch(void* const* d_in, const int* in_sizes, int n_in,
                              void* d_out, int out_size)
{
    const float* x   = (const float*)d_in[0];
    const float* Wq  = (const float*)d_in[1];
    const float* bq  = (const float*)d_in[2];
    const float* Wk  = (const float*)d_in[3];
    const float* bk  = (const float*)d_in[4];
    const float* Wv  = (const float*)d_in[5];
    const float* bv  = (const float*)d_in[6];
    const float* Wo  = (const float*)d_in[7];
    const float* bo  = (const float*)d_in[8];
    const float* qns = (const float*)d_in[9];
    const float* kns = (const float*)d_in[10];
    float* out = (float*)d_out;

    __half *xhi, *aoh, *wh, *woh;
    __half *qah, *kah, *vah;
    float* bqkv;
    cudaGetSymbolAddress((void**)&xhi, g_xhi);
    cudaGetSymbolAddress((void**)&aoh, g_aoh);
    cudaGetSymbolAddress((void**)&wh,  g_wh);
    cudaGetSymbolAddress((void**)&woh, g_woh);
    cudaGetSymbolAddress((void**)&bqkv, g_bqkv);
    cudaGetSymbolAddress((void**)&qah, g_qah);
    cudaGetSymbolAddress((void**)&kah, g_kah);
    cudaGetSymbolAddress((void**)&vah, g_vah);

    cudaFuncSetAttribute(gemm_qkv, cudaFuncAttributeMaxDynamicSharedMemorySize, QGEMM_SMEM);
    cudaFuncSetAttribute(gemm_wo, cudaFuncAttributeMaxDynamicSharedMemorySize, QGEMM_SMEM);
    cudaFuncSetAttribute(flash_attn_hmma, cudaFuncAttributeMaxDynamicSharedMemorySize, FA_SMEM);

    // feeders: ONE launch (x convert + all weight transposes + bias concat)
    prep_all<<<PREP_TOTAL, 256>>>(x, Wq, Wk, Wv, Wo, bq, bk, bv,
                                  xhi, wh, woh, bqkv);

    // fused QKV projection + rmsnorm + rope (q carries full 1/hd)
    gemm_qkv<<<dim3(NQKV / BN, MROWS / BM), 256, QGEMM_SMEM>>>(
        xhi, wh, bqkv, qns, kns, qah, kah, vah);

    // attention (HMMA, plain fp16, BR=64, 2 CTAs/SM, reg-resident Q)
    flash_attn_hmma<<<dim3(SEQ / 64, NH, BATCH), 128, FA_SMEM>>>(
        qah, kah, vah, aoh);

    // output projection (plain fp16)
    gemm_wo<<<dim3(DIM / BN, MROWS / BM), 256, QGEMM_SMEM>>>(
        aoh, woh, bo, out, DIM);
}

// round 17
// speedup vs baseline: 1.0841x; 1.0110x over previous
#include <cuda_runtime.h>
#include <cuda_fp16.h>
#include <cstdint>
#include <math.h>

#define BATCH 16
#define SEQ   512
#define DIM   2048
#define NH    16
#define NG    4
#define HD    128
#define MROWS (BATCH*SEQ)   // 8192
#define KVD   (NG*HD)       // 512
#define NQKV  (DIM + 2*KVD) // 3072

// ---------------------------------------------------------------------------
// scratch (device globals — no allocation allowed)
// ---------------------------------------------------------------------------
__device__ __half g_xhi[(size_t)MROWS * DIM];
__device__ __half g_aoh[(size_t)MROWS * DIM];   // attn out fp16 (b,s,H,hd)
__device__ __half g_wh[(size_t)NQKV * DIM];     // [Wq^T; Wk^T; Wv^T] fp16
__device__ __half g_woh[(size_t)DIM * DIM];     // Wo^T fp16
__device__ float  g_bqkv[NQKV];                 // [bq; bk; bv]

// attention operand buffers, (b, head, s, hd) layout, plain fp16
__device__ __half g_qah[(size_t)MROWS * DIM];
__device__ __half g_kah[(size_t)MROWS * KVD];
__device__ __half g_vah[(size_t)MROWS * KVD];

// ---------------------------------------------------------------------------
// helpers
// ---------------------------------------------------------------------------
__device__ __forceinline__ uint32_t smem_to_u32(const void* p) {
    uint32_t a;
    asm("{ .reg .u64 t; cvta.to.shared.u64 t, %1; cvt.u32.u64 %0, t; }" : "=r"(a) : "l"(p));
    return a;
}
#define SMEM_SWIZZLE_128B(bo) ((bo) ^ (((bo) >> 3) & 0x70))

__device__ __forceinline__ void cp16(uint32_t s, const void* g) {
    asm volatile("cp.async.cg.shared.global [%0], [%1], 16;" :: "r"(s), "l"(g) : "memory");
}
#define CP_COMMIT() asm volatile("cp.async.commit_group;" ::: "memory")
#define CP_WAIT2()  asm volatile("cp.async.wait_group 2;" ::: "memory")
#define CP_WAIT1()  asm volatile("cp.async.wait_group 1;" ::: "memory")
#define CP_WAIT0()  asm volatile("cp.async.wait_group 0;" ::: "memory")
__device__ __forceinline__ void ldm4(uint32_t* r, uint32_t a) {
    asm volatile("ldmatrix.sync.aligned.m8n8.x4.shared.b16 {%0,%1,%2,%3}, [%4];"
                 : "=r"(r[0]), "=r"(r[1]), "=r"(r[2]), "=r"(r[3]) : "r"(a));
}
__device__ __forceinline__ void ldm4t(uint32_t* r, uint32_t a) {
    asm volatile("ldmatrix.sync.aligned.m8n8.x4.trans.shared.b16 {%0,%1,%2,%3}, [%4];"
                 : "=r"(r[0]), "=r"(r[1]), "=r"(r[2]), "=r"(r[3]) : "r"(a));
}
__device__ __forceinline__ void mma16816(float* d, const uint32_t* a, const uint32_t* b) {
    asm volatile(
        "mma.sync.aligned.m16n8k16.row.col.f32.f16.f16.f32 "
        "{%0,%1,%2,%3},{%4,%5,%6,%7},{%8,%9},{%0,%1,%2,%3};"
        : "+f"(d[0]), "+f"(d[1]), "+f"(d[2]), "+f"(d[3])
        : "r"(a[0]), "r"(a[1]), "r"(a[2]), "r"(a[3]), "r"(b[0]), "r"(b[1]));
}
__device__ __forceinline__ uint32_t pk2h(float a, float b) {
    __half2 h = __floats2half2_rn(a, b);
    return *reinterpret_cast<uint32_t*>(&h);
}

// ---------------------------------------------------------------------------
// Fused prep (ONE launch): x fp32->fp16, weight transpose+convert, bias concat
// ---------------------------------------------------------------------------
#define PREP_XBLK 16384
#define PREP_WBLK 10240
#define PREP_TOTAL (PREP_XBLK + PREP_WBLK + (NQKV + 255) / 256)

__global__ __launch_bounds__(256) void prep_all(
    const float* __restrict__ x,
    const float* __restrict__ Wq, const float* __restrict__ Wk,
    const float* __restrict__ Wv, const float* __restrict__ Wo,
    const float* __restrict__ bq, const float* __restrict__ bk,
    const float* __restrict__ bv,
    __half* __restrict__ xhi,
    __half* __restrict__ wh, __half* __restrict__ woh,
    float* __restrict__ bqkv)
{
    int id = blockIdx.x;
    if (id < PREP_XBLK) {
        int i = id * 256 + threadIdx.x;
        float4 v = ((const float4*)x)[i];
        uint2 ph;
        ph.x = pk2h(v.x, v.y); ph.y = pk2h(v.z, v.w);
        ((uint2*)xhi)[i] = ph;
        return;
    }
    id -= PREP_XBLK;
    if (id >= PREP_WBLK) {
        int i = (id - PREP_WBLK) * 256 + threadIdx.x;
        if (i < DIM) bqkv[i] = bq[i];
        else if (i < DIM + KVD) bqkv[i] = bk[i - DIM];
        else if (i < NQKV) bqkv[i] = bv[i - DIM - KVD];
        return;
    }

    const float* W;
    __half* T;
    int N, nb, base;
    if (id < 4096)      { W = Wq; T = wh;                              N = DIM; nb = 64; base = 0; }
    else if (id < 5120) { W = Wk; T = wh + (size_t)DIM * DIM;          N = KVD; nb = 16; base = 4096; }
    else if (id < 6144) { W = Wv; T = wh + (size_t)(DIM + KVD) * DIM;  N = KVD; nb = 16; base = 5120; }
    else                { W = Wo; T = woh;                             N = DIM; nb = 64; base = 6144; }
    int lid = id - base;
    int n0 = (lid % nb) * 32;
    int k0 = (lid / nb) * 32;

    __shared__ float tile[32][33];
    int tx = threadIdx.x & 31, ty = threadIdx.x >> 5;
    #pragma unroll
    for (int j = ty; j < 32; j += 8)
        tile[j][tx] = W[(size_t)(k0 + j) * N + n0 + tx];
    __syncthreads();
    #pragma unroll
    for (int j = ty; j < 32; j += 8)
        T[(size_t)(n0 + j) * DIM + k0 + tx] = __float2half_rn(tile[tx][j]);
}

// ---------------------------------------------------------------------------
// tile config — plain fp16 GEMM, 128 threads (4 warps, 2x2), warp tile 64x64
// stage = AH 16K + BH 16K, 3-stage, 2 CTAs/SM
// ---------------------------------------------------------------------------
#define BM 128
#define BN 128
#define BK 64
#define NCH (DIM / BK)   // 32
#define QSTG_BYTES 32768
#define Q_OFF_AH 0
#define Q_OFF_BH 16384
#define QGEMM_SMEM (3 * QSTG_BYTES)   // 98304
#define GTH 128

// mainloop (leaves accum in d[4][8][4]); warp (wm,wn) owns rows wm*64+.., cols wn*64+..
#define GEMM_MAIN(Ahg, Bhg)                                                        \
    auto load_stage = [&](int s, int kt) {                                         \
        int k0 = kt * BK;                                                          \
        uint32_t base = sb + s * QSTG_BYTES;                                       \
        _Pragma("unroll")                                                          \
        for (int t = 0; t < 8; t++) {                                              \
            int idx = tid + t * GTH;                                               \
            int r = idx >> 3, c16 = idx & 7;                                       \
            uint32_t swz = SMEM_SWIZZLE_128B((uint32_t)(r * 128 + c16 * 16));      \
            cp16(base + Q_OFF_AH + swz, Ahg + (size_t)(by + r) * DIM + k0 + c16 * 8); \
            cp16(base + Q_OFF_BH + swz, Bhg + (size_t)(bx + r) * DIM + k0 + c16 * 8); \
        }                                                                          \
    };                                                                             \
    float d[4][8][4];                                                              \
    _Pragma("unroll")                                                              \
    for (int i = 0; i < 4; i++)                                                    \
        _Pragma("unroll")                                                          \
        for (int j = 0; j < 8; j++)                                                \
            _Pragma("unroll")                                                      \
            for (int q = 0; q < 4; q++) d[i][j][q] = 0.f;                          \
    load_stage(0, 0); CP_COMMIT();                                                 \
    load_stage(1, 1); CP_COMMIT();                                                 \
    load_stage(2, 2); CP_COMMIT();                                                 \
    for (int kt = 0; kt < NCH; kt++) {                                             \
        CP_WAIT2();                                                                \
        __syncthreads();                                                           \
        int s = kt % 3;                                                            \
        uint32_t base = sb + s * QSTG_BYTES;                                       \
        int arow = wm * 64 + (lane & 15);                                          \
        int bro  = wn * 64 + (lane & 7) + ((lane >> 4) << 3);                      \
        int bkh  = ((lane >> 3) & 1) << 3;                                         \
        _Pragma("unroll")                                                          \
        for (int ks = 0; ks < 4; ks++) {                                           \
            int acol = ks * 16 + ((lane >> 4) << 3);                               \
            uint32_t ah[4][4], bh[8][2];                                           \
            _Pragma("unroll")                                                      \
            for (int mf = 0; mf < 4; mf++) {                                       \
                uint32_t off = SMEM_SWIZZLE_128B(                                  \
                    (uint32_t)((arow + mf * 16) * 128 + acol * 2));                \
                ldm4(ah[mf], base + Q_OFF_AH + off);                               \
            }                                                                      \
            _Pragma("unroll")                                                      \
            for (int j2 = 0; j2 < 4; j2++) {                                       \
                uint32_t off = SMEM_SWIZZLE_128B(                                  \
                    (uint32_t)((bro + j2 * 16) * 128 + (ks * 16 + bkh) * 2));      \
                uint32_t r[4];                                                     \
                ldm4(r, base + Q_OFF_BH + off);                                    \
                bh[j2 * 2][0] = r[0]; bh[j2 * 2][1] = r[1];                        \
                bh[j2 * 2 + 1][0] = r[2]; bh[j2 * 2 + 1][1] = r[3];                \
            }                                                                      \
            _Pragma("unroll")                                                      \
            for (int mf = 0; mf < 4; mf++)                                         \
                _Pragma("unroll")                                                  \
                for (int nf = 0; nf < 8; nf++)                                     \
                    mma16816(d[mf][nf], ah[mf], bh[nf]);                           \
        }                                                                          \
        __syncthreads();                                                           \
        if (kt + 3 < NCH) load_stage(s, kt + 3);                                   \
        CP_COMMIT();                                                               \
    }

// ---------------------------------------------------------------------------
// Fused QKV GEMM + RMSNorm + RoPE epilogue.
// ---------------------------------------------------------------------------
__global__ __launch_bounds__(GTH, 2) void gemm_qkv(
    const __half* __restrict__ Ahg, const __half* __restrict__ Bhg,
    const float* __restrict__ bias,
    const float* __restrict__ qns, const float* __restrict__ kns,
    __half* __restrict__ qah, __half* __restrict__ kah,
    __half* __restrict__ vah)
{
    extern __shared__ char sm[];
    uint32_t sb = smem_to_u32(sm);
    int tid = threadIdx.x, lane = tid & 31, wid = tid >> 5;
    int wm = wid & 1, wn = wid >> 1;          // 2 x 2 warps
    int bx = blockIdx.x * BN, by = blockIdx.y * BM;

    GEMM_MAIN(Ahg, Bhg)

    // ---------------- fused epilogue ----------------
    int hb = blockIdx.x;             // 0..23
    bool needs_norm = (hb < 20);

    int c0 = wn * 64 + (lane & 3) * 2;
    #pragma unroll
    for (int mf = 0; mf < 4; mf++)
        #pragma unroll
        for (int nf = 0; nf < 8; nf++) {
            int c = c0 + nf * 8;
            float b0 = bias[bx + c], b1 = bias[bx + c + 1];
            d[mf][nf][0] += b0; d[mf][nf][1] += b1;
            d[mf][nf][2] += b0; d[mf][nf][3] += b1;
        }

    float* ss = (float*)sm;          // [128][2] partial row sums
    __syncthreads();                 // stage reads done

    if (needs_norm) {
        #pragma unroll
        for (int mf = 0; mf < 4; mf++) {
            float pA = 0.f, pB = 0.f;
            #pragma unroll
            for (int nf = 0; nf < 8; nf++) {
                pA += d[mf][nf][0] * d[mf][nf][0] + d[mf][nf][1] * d[mf][nf][1];
                pB += d[mf][nf][2] * d[mf][nf][2] + d[mf][nf][3] * d[mf][nf][3];
            }
            pA += __shfl_xor_sync(0xffffffffu, pA, 1);
            pA += __shfl_xor_sync(0xffffffffu, pA, 2);
            pB += __shfl_xor_sync(0xffffffffu, pB, 1);
            pB += __shfl_xor_sync(0xffffffffu, pB, 2);
            if ((lane & 3) == 0) {
                int lr = wm * 64 + mf * 16 + (lane >> 2);
                ss[lr * 2 + wn] = pA;
                ss[(lr + 8) * 2 + wn] = pB;
            }
        }
    }
    __syncthreads();

    const float* nsc = (hb < 16) ? qns : kns;
    float esc = (hb < 16) ? (1.0f / (float)HD) : 1.0f;
    __half* oph;
    int headmul;
    if (hb < 16)      { oph = qah; headmul = NH; }
    else if (hb < 20) { oph = kah; headmul = NG; }
    else              { oph = vah; headmul = NG; }
    int head = (hb < 16) ? hb : ((hb < 20) ? hb - 16 : hb - 20);

    #pragma unroll
    for (int mf = 0; mf < 4; mf++) {
        int lr = wm * 64 + mf * 16 + (lane >> 2);
        int rowA = by + lr, rowB = rowA + 8;
        int posA = rowA & (SEQ - 1), posB = rowB & (SEQ - 1);
        int bA = rowA >> 9, bB = rowB >> 9;
        float rinvA = 1.f, rinvB = 1.f;
        if (needs_norm) {
            float sA = ss[lr * 2] + ss[lr * 2 + 1];
            float sB = ss[(lr + 8) * 2] + ss[(lr + 8) * 2 + 1];
            rinvA = rsqrtf(sA * (1.0f / HD) + 1e-6f);
            rinvB = rsqrtf(sB * (1.0f / HD) + 1e-6f);
        }
        size_t obA = ((size_t)(bA * headmul + head) * SEQ + posA) * HD;
        size_t obB = ((size_t)(bB * headmul + head) * SEQ + posB) * HD;
        #pragma unroll
        for (int nf = 0; nf < 8; nf++) {
            int c = c0 + nf * 8;
            if (needs_norm) {
                float sc0 = nsc[c], sc1 = nsc[c + 1];
                float invf = __expf(-(float)(c >> 1) * (9.210340371976184f / 64.0f));
                float snA, csA, snB, csB;
                __sincosf((float)posA * invf, &snA, &csA);
                __sincosf((float)posB * invf, &snB, &csB);
                float xA1 = d[mf][nf][0] * rinvA * sc0;
                float xA2 = d[mf][nf][1] * rinvA * sc1;
                float xB1 = d[mf][nf][2] * rinvB * sc0;
                float xB2 = d[mf][nf][3] * rinvB * sc1;
                *(__half2*)&oph[obA + c] = __floats2half2_rn(
                    (xA1 * csA - xA2 * snA) * esc, (xA1 * snA + xA2 * csA) * esc);
                *(__half2*)&oph[obB + c] = __floats2half2_rn(
                    (xB1 * csB - xB2 * snB) * esc, (xB1 * snB + xB2 * csB) * esc);
            } else {
                *(__half2*)&vah[obA + c] = __floats2half2_rn(d[mf][nf][0], d[mf][nf][1]);
                *(__half2*)&vah[obB + c] = __floats2half2_rn(d[mf][nf][2], d[mf][nf][3]);
            }
        }
    }
}

// ---------------------------------------------------------------------------
// Wo GEMM: plain fp16 single-product, bias, fp32 output.
// ---------------------------------------------------------------------------
__global__ __launch_bounds__(GTH, 2) void gemm_wo(
    const __half* __restrict__ Ahg, const __half* __restrict__ Bhg,
    const float* __restrict__ bias, float* __restrict__ C, int N)
{
    extern __shared__ char sm[];
    uint32_t sb = smem_to_u32(sm);
    int tid = threadIdx.x, lane = tid & 31, wid = tid >> 5;
    int wm = wid & 1, wn = wid >> 1;
    int bx = blockIdx.x * BN, by = blockIdx.y * BM;

    GEMM_MAIN(Ahg, Bhg)

    int row0 = by + wm * 64 + (lane >> 2);
    int col0 = bx + wn * 64 + (lane & 3) * 2;
    #pragma unroll
    for (int mf = 0; mf < 4; mf++)
        #pragma unroll
        for (int nf = 0; nf < 8; nf++) {
            int r = row0 + mf * 16;
            int c = col0 + nf * 8;
            float b0 = bias[c], b1 = bias[c + 1];
            float2 v0 = make_float2(d[mf][nf][0] + b0, d[mf][nf][1] + b1);
            float2 v1 = make_float2(d[mf][nf][2] + b0, d[mf][nf][3] + b1);
            *(float2*)&C[(size_t)r * N + c] = v0;
            *(float2*)&C[(size_t)(r + 8) * N + c] = v1;
        }
}

// ---------------------------------------------------------------------------
// HMMA flash attention (unchanged from R16). BR=64, 4 warps, 2-stage, 2 CTAs/SM,
// Q register-resident. smem: 16KB + 2x32KB = 80KB
// ---------------------------------------------------------------------------
#define FA_STG 32768
#define FA_SMEM (16384 + 2 * FA_STG)   // 81920

__global__ __launch_bounds__(128, 2) void flash_attn_hmma(
    const __half* __restrict__ qh, const __half* __restrict__ kh,
    const __half* __restrict__ vh, __half* __restrict__ aoh)
{
    extern __shared__ char sm[];
    uint32_t sb = smem_to_u32(sm);
    int qb = (gridDim.x - 1) - blockIdx.x;
    int h = blockIdx.y, b = blockIdx.z;
    int g = h >> 2;
    int tid = threadIdx.x, lane = tid & 31, wid = tid >> 5;

    const size_t qbase  = ((size_t)(b * NH + h) * SEQ + qb * 64) * HD;
    const size_t kvbase = ((size_t)(b * NG + g) * SEQ) * HD;

    const uint32_t QH = sb;

    auto load_q = [&]() {
        #pragma unroll
        for (int t = 0; t < 8; t++) {
            int idx = tid + t * 128;
            int r = idx >> 4, c16 = idx & 15;
            uint32_t off = (uint32_t)((c16 >> 3) * 8192) +
                           SMEM_SWIZZLE_128B((uint32_t)(r * 128 + (c16 & 7) * 16));
            cp16(QH + off, qh + qbase + (size_t)r * HD + c16 * 8);
        }
    };
    auto load_kv = [&](int s, int kt) {
        uint32_t base = sb + 16384 + s * FA_STG;
        size_t kb = kvbase + (size_t)kt * 64 * HD;
        #pragma unroll
        for (int t = 0; t < 8; t++) {
            int idx = tid + t * 128;
            int r = idx >> 4, c16 = idx & 15;
            uint32_t off = (uint32_t)((c16 >> 3) * 8192) +
                           SMEM_SWIZZLE_128B((uint32_t)(r * 128 + (c16 & 7) * 16));
            size_t go = kb + (size_t)r * HD + c16 * 8;
            cp16(base + off,         kh + go);
            cp16(base + 16384 + off, vh + go);
        }
    };

    int nkt = qb + 1;
    load_q();
    load_kv(0, 0);
    CP_COMMIT();
    if (1 < nkt) load_kv(1, 1);
    CP_COMMIT();

    CP_WAIT1();
    __syncthreads();
    int row0 = wid * 16;
    uint32_t qf[8][4];
    {
        int aro = row0 + (lane & 15);
        #pragma unroll
        for (int ks = 0; ks < 8; ks++) {
            int chk  = ks >> 2;
            int acol = (ks & 3) * 16 + ((lane >> 4) << 3);
            uint32_t aoff = (uint32_t)(chk * 8192) +
                            SMEM_SWIZZLE_128B((uint32_t)(aro * 128 + acol * 2));
            ldm4(qf[ks], QH + aoff);
        }
    }

    float o[16][4];
    #pragma unroll
    for (int i = 0; i < 16; i++)
        #pragma unroll
        for (int j = 0; j < 4; j++) o[i][j] = 0.f;
    float mA = -1e30f, mB = -1e30f, lA = 0.f, lB = 0.f;

    int sq = qb * 64 + row0;

    for (int kt = 0; kt < nkt; kt++) {
        if (kt < nkt - 1) CP_WAIT1(); else CP_WAIT0();
        __syncthreads();

        int st = kt & 1;
        uint32_t KHb = sb + 16384 + st * FA_STG;
        uint32_t VHb = KHb + 16384;

        {
            float sc[8][4];
            #pragma unroll
            for (int i = 0; i < 8; i++)
                #pragma unroll
                for (int j = 0; j < 4; j++) sc[i][j] = 0.f;

            int kro  = (lane & 7) + ((lane >> 4) << 3);
            int bkh  = ((lane >> 3) & 1) << 3;

            #pragma unroll
            for (int ks = 0; ks < 8; ks++) {
                int chk  = ks >> 2;
                int bcol = (ks & 3) * 16 + bkh;
                uint32_t bh[8][2];
                #pragma unroll
                for (int j2 = 0; j2 < 4; j2++) {
                    uint32_t boff = (uint32_t)(chk * 8192) +
                        SMEM_SWIZZLE_128B((uint32_t)((j2 * 16 + kro) * 128 + bcol * 2));
                    uint32_t r[4];
                    ldm4(r, KHb + boff);
                    bh[2*j2][0] = r[0]; bh[2*j2][1] = r[1];
                    bh[2*j2+1][0] = r[2]; bh[2*j2+1][1] = r[3];
                }
                #pragma unroll
                for (int nf = 0; nf < 8; nf++)
                    mma16816(sc[nf], qf[ks], bh[nf]);
            }

            if (kt * 64 + 63 > sq) {
                int rA = sq + (lane >> 2), rB = rA + 8;
                #pragma unroll
                for (int nf = 0; nf < 8; nf++) {
                    int cbase = kt * 64 + nf * 8 + 2 * (lane & 3);
                    if (cbase     > rA) sc[nf][0] = -1e30f;
                    if (cbase + 1 > rA) sc[nf][1] = -1e30f;
                    if (cbase     > rB) sc[nf][2] = -1e30f;
                    if (cbase + 1 > rB) sc[nf][3] = -1e30f;
                }
            }

            float mtA = -1e30f, mtB = -1e30f;
            #pragma unroll
            for (int nf = 0; nf < 8; nf++) {
                mtA = fmaxf(mtA, fmaxf(sc[nf][0], sc[nf][1]));
                mtB = fmaxf(mtB, fmaxf(sc[nf][2], sc[nf][3]));
            }
            mtA = fmaxf(mtA, __shfl_xor_sync(0xffffffffu, mtA, 1));
            mtA = fmaxf(mtA, __shfl_xor_sync(0xffffffffu, mtA, 2));
            mtB = fmaxf(mtB, __shfl_xor_sync(0xffffffffu, mtB, 1));
            mtB = fmaxf(mtB, __shfl_xor_sync(0xffffffffu, mtB, 2));
            float nmA = fmaxf(mA, mtA), nmB = fmaxf(mB, mtB);
            float alA = __expf(mA - nmA), alB = __expf(mB - nmB);

            float suA = 0.f, suB = 0.f;
            #pragma unroll
            for (int nf = 0; nf < 8; nf++) {
                sc[nf][0] = __expf(sc[nf][0] - nmA); suA += sc[nf][0];
                sc[nf][1] = __expf(sc[nf][1] - nmA); suA += sc[nf][1];
                sc[nf][2] = __expf(sc[nf][2] - nmB); suB += sc[nf][2];
                sc[nf][3] = __expf(sc[nf][3] - nmB); suB += sc[nf][3];
            }
            suA += __shfl_xor_sync(0xffffffffu, suA, 1);
            suA += __shfl_xor_sync(0xffffffffu, suA, 2);
            suB += __shfl_xor_sync(0xffffffffu, suB, 1);
            suB += __shfl_xor_sync(0xffffffffu, suB, 2);
            lA = lA * alA + suA;
            lB = lB * alB + suB;
            mA = nmA; mB = nmB;
            #pragma unroll
            for (int nf = 0; nf < 16; nf++) {
                o[nf][0] *= alA; o[nf][1] *= alA;
                o[nf][2] *= alB; o[nf][3] *= alB;
            }

            int vro = (lane & 7) + (((lane >> 3) & 1) << 3);
            int vch = (lane >> 4) << 3;
            #pragma unroll
            for (int kf = 0; kf < 4; kf++) {
                uint32_t aPh[4];
                aPh[0] = pk2h(sc[2*kf][0],   sc[2*kf][1]);
                aPh[1] = pk2h(sc[2*kf][2],   sc[2*kf][3]);
                aPh[2] = pk2h(sc[2*kf+1][0], sc[2*kf+1][1]);
                aPh[3] = pk2h(sc[2*kf+1][2], sc[2*kf+1][3]);
                #pragma unroll
                for (int j2 = 0; j2 < 8; j2++) {
                    int chk  = j2 >> 2;
                    int wcol = (j2 & 3) * 16 + vch;
                    uint32_t voff = (uint32_t)(chk * 8192) +
                        SMEM_SWIZZLE_128B((uint32_t)((kf * 16 + vro) * 128 + wcol * 2));
                    uint32_t rh[4];
                    ldm4t(rh, VHb + voff);
                    uint32_t bh0[2] = {rh[0], rh[1]}, bh1[2] = {rh[2], rh[3]};
                    mma16816(o[2*j2],   aPh, bh0);
                    mma16816(o[2*j2+1], aPh, bh1);
                }
            }
        }
        __syncthreads();

        if (kt + 2 < nkt) load_kv(kt & 1, kt + 2);
        CP_COMMIT();
    }

    float rlA = 1.0f / lA, rlB = 1.0f / lB;
    int sA = sq + (lane >> 2), sB = sA + 8;
    size_t oA = ((size_t)(b * SEQ + sA) * NH + h) * HD;
    size_t oB = ((size_t)(b * SEQ + sB) * NH + h) * HD;
    #pragma unroll
    for (int nf = 0; nf < 16; nf++) {
        int hd = nf * 8 + 2 * (lane & 3);
        *(__half2*)&aoh[oA + hd] = __floats2half2_rn(o[nf][0] * rlA, o[nf][1] * rlA);
        *(__half2*)&aoh[oB + hd] = __floats2half2_rn(o[nf][2] * rlB, o[nf][3] * rlB);
    }
}

// ---------------------------------------------------------------------------
extern "C" void kernel_launch(void* const* d_in, const int* in_sizes, int n_in,
                              void* d_out, int out_size)
{
    const float* x   = (const float*)d_in[0];
    const float* Wq  = (const float*)d_in[1];
    const float* bq  = (const float*)d_in[2];
    const float* Wk  = (const float*)d_in[3];
    const float* bk  = (const float*)d_in[4];
    const float* Wv  = (const float*)d_in[5];
    const float* bv  = (const float*)d_in[6];
    const float* Wo  = (const float*)d_in[7];
    const float* bo  = (const float*)d_in[8];
    const float* qns = (const float*)d_in[9];
    const float* kns = (const float*)d_in[10];
    float* out = (float*)d_out;

    __half *xhi, *aoh, *wh, *woh;
    __half *qah, *kah, *vah;
    float* bqkv;
    cudaGetSymbolAddress((void**)&xhi, g_xhi);
    cudaGetSymbolAddress((void**)&aoh, g_aoh);
    cudaGetSymbolAddress((void**)&wh,  g_wh);
    cudaGetSymbolAddress((void**)&woh, g_woh);
    cudaGetSymbolAddress((void**)&bqkv, g_bqkv);
    cudaGetSymbolAddress((void**)&qah, g_qah);
    cudaGetSymbolAddress((void**)&kah, g_kah);
    cudaGetSymbolAddress((void**)&vah, g_vah);

    cudaFuncSetAttribute(gemm_qkv, cudaFuncAttributeMaxDynamicSharedMemorySize, QGEMM_SMEM);
    cudaFuncSetAttribute(gemm_wo, cudaFuncAttributeMaxDynamicSharedMemorySize, QGEMM_SMEM);
    cudaFuncSetAttribute(flash_attn_hmma, cudaFuncAttributeMaxDynamicSharedMemorySize, FA_SMEM);

    // feeders: ONE launch
    prep_all<<<PREP_TOTAL, 256>>>(x, Wq, Wk, Wv, Wo, bq, bk, bv,
                                  xhi, wh, woh, bqkv);

    // fused QKV projection + rmsnorm + rope (q carries full 1/hd)
    gemm_qkv<<<dim3(NQKV / BN, MROWS / BM), GTH, QGEMM_SMEM>>>(
        xhi, wh, bqkv, qns, kns, qah, kah, vah);

    // attention (HMMA, plain fp16, BR=64, 2 CTAs/SM, reg-resident Q)
    flash_attn_hmma<<<dim3(SEQ / 64, NH, BATCH), 128, FA_SMEM>>>(
        qah, kah, vah, aoh);

    // output projection (plain fp16)
    gemm_wo<<<dim3(DIM / BN, MROWS / BM), GTH, QGEMM_SMEM>>>(
        aoh, woh, bo, out, DIM);
}